// round 5
// baseline (speedup 1.0000x reference)
#include <cuda_runtime.h>
#include <cuda_bf16.h>
#include <cstdint>

#define SEQ 4096
#define DM  1024
#define NH  16
#define DH  64
#define WIN 256

// ---------------------------------------------------------------------------
// Scratch (allocation-free rule)
// ---------------------------------------------------------------------------
__device__ float g_q[SEQ * DM];
__device__ float g_k[SEQ * DM];
__device__ float g_v[SEQ * DM];
__device__ __nv_bfloat16 g_xh[SEQ * DM], g_xl[SEQ * DM];      // x split planes
__device__ __nv_bfloat16 g_ah[SEQ * DM], g_al[SEQ * DM];      // attn-out planes
__device__ __nv_bfloat16 g_wh[4][DM * DM], g_wl[4][DM * DM];  // W^T planes (q,k,v,o)

// ---------------------------------------------------------------------------
// Helpers
// ---------------------------------------------------------------------------
__device__ __forceinline__ uint32_t smem_u32(const void* p) {
    uint32_t a;
    asm("{ .reg .u64 t; cvta.to.shared.u64 t, %1; cvt.u32.u64 %0, t; }" : "=r"(a) : "l"(p));
    return a;
}
__device__ __forceinline__ unsigned f2tf(float f) {
    unsigned r; asm("cvt.rna.tf32.f32 %0, %1;" : "=r"(r) : "f"(f)); return r;
}
__device__ __forceinline__ void split_pair(float x, float y, unsigned& hi, unsigned& lo) {
    __nv_bfloat16 hx = __float2bfloat16(x), hy = __float2bfloat16(y);
    __nv_bfloat16 lx = __float2bfloat16(x - __bfloat162float(hx));
    __nv_bfloat16 ly = __float2bfloat16(y - __bfloat162float(hy));
    __nv_bfloat162 h; h.x = hx; h.y = hy;
    __nv_bfloat162 l; l.x = lx; l.y = ly;
    hi = *(unsigned*)&h; lo = *(unsigned*)&l;
}
__device__ __forceinline__ void mma_bf(float* c, const unsigned* a, const unsigned* b) {
    asm volatile("mma.sync.aligned.m16n8k16.row.col.f32.bf16.bf16.f32 "
        "{%0,%1,%2,%3},{%4,%5,%6,%7},{%8,%9},{%0,%1,%2,%3};"
        : "+f"(c[0]), "+f"(c[1]), "+f"(c[2]), "+f"(c[3])
        : "r"(a[0]), "r"(a[1]), "r"(a[2]), "r"(a[3]), "r"(b[0]), "r"(b[1]));
}
__device__ __forceinline__ void mma_tf(float* c, const unsigned* a, const unsigned* b) {
    asm volatile("mma.sync.aligned.m16n8k8.row.col.f32.tf32.tf32.f32 "
        "{%0,%1,%2,%3},{%4,%5,%6,%7},{%8,%9},{%0,%1,%2,%3};"
        : "+f"(c[0]), "+f"(c[1]), "+f"(c[2]), "+f"(c[3])
        : "r"(a[0]), "r"(a[1]), "r"(a[2]), "r"(a[3]), "r"(b[0]), "r"(b[1]));
}
#define CP16(dst, src) \
    asm volatile("cp.async.cg.shared.global [%0], [%1], 16;" :: "r"(dst), "l"(src))
#define CP_COMMIT() asm volatile("cp.async.commit_group;" ::: "memory")
#define CP_WAIT2()  asm volatile("cp.async.wait_group 2;" ::: "memory")
#define LDSM4(r0, r1, r2, r3, a) \
    asm volatile("ldmatrix.sync.aligned.m8n8.x4.shared.b16 {%0,%1,%2,%3}, [%4];" \
        : "=r"(r0), "=r"(r1), "=r"(r2), "=r"(r3) : "r"(a))

// ---------------------------------------------------------------------------
// Conversion kernels (one-time per launch)
// ---------------------------------------------------------------------------
__global__ void split_plain(const float* __restrict__ src,
                            __nv_bfloat16* __restrict__ hi, __nv_bfloat16* __restrict__ lo) {
    int i = (blockIdx.x * blockDim.x + threadIdx.x) * 4;
    float4 v = *(const float4*)(src + i);
    unsigned h0, l0, h1, l1;
    split_pair(v.x, v.y, h0, l0);
    split_pair(v.z, v.w, h1, l1);
    *(uint2*)(hi + i) = make_uint2(h0, h1);
    *(uint2*)(lo + i) = make_uint2(l0, l1);
}

// W [K=DM][N=DM] -> hT/lT [N][K] bf16 planes
__global__ void tsplit(const float* __restrict__ W,
                       __nv_bfloat16* __restrict__ hT, __nv_bfloat16* __restrict__ lT) {
    __shared__ float tile[32][33];
    int k0 = blockIdx.y * 32, n0 = blockIdx.x * 32;
    int tx = threadIdx.x, ty = threadIdx.y;
#pragma unroll
    for (int j = 0; j < 32; j += 8)
        tile[ty + j][tx] = W[(size_t)(k0 + ty + j) * DM + n0 + tx];
    __syncthreads();
#pragma unroll
    for (int j = 0; j < 32; j += 8) {
        float v = tile[tx][ty + j];
        __nv_bfloat16 h = __float2bfloat16(v);
        size_t o = (size_t)(n0 + ty + j) * DM + k0 + tx;
        hT[o] = h;
        lT[o] = __float2bfloat16(v - __bfloat162float(h));
    }
}

// ---------------------------------------------------------------------------
// Pipelined bf16x2 HMMA GEMM on precomputed planes.
// C[row0:+128, ncols] tiles; A planes [M][K], B^T planes [N][K], both bf16.
// 256 threads (8 warps, 2x4), warp tile 64x32, BK=16, 3-stage cp.async ring.
// Smem rows padded to 48B (conflict-free for ldmatrix & cp.async).
// Output pointer selected per 1024-col group (QKV fusion).
// ---------------------------------------------------------------------------
#define ROWB    48
#define PLANEB  (128 * ROWB)        // 6144
#define STAGEB  (4 * PLANEB)        // 24576
#define NSTAGE  3
#define GSMEM   (NSTAGE * STAGEB)   // 73728

__global__ void __launch_bounds__(256, 2) gemm_planes(
    const __nv_bfloat16* __restrict__ Ah, const __nv_bfloat16* __restrict__ Al,
    const __nv_bfloat16* __restrict__ BhT, const __nv_bfloat16* __restrict__ BlT,
    float* __restrict__ O0, float* __restrict__ O1, float* __restrict__ O2)
{
    extern __shared__ char dynsmem[];
    const uint32_t sb = smem_u32(dynsmem);
    const int tid = threadIdx.x, lane = tid & 31, warp = tid >> 5;
    const int m0 = blockIdx.y * 128;
    const int nb = blockIdx.x;
    const int nbase = nb * 128;
    float* out = (nb >> 3) == 0 ? O0 : ((nb >> 3) == 1 ? O1 : O2);
    const int col0 = (nb & 7) * 128;

    // cp.async task: thread -> (row r, 16B half hf) for each of the 4 planes
    const int r = tid >> 1, hf = tid & 1;
    const __nv_bfloat16* gsrc0 = Ah  + (size_t)(m0 + r) * DM + hf * 8;
    const __nv_bfloat16* gsrc1 = Al  + (size_t)(m0 + r) * DM + hf * 8;
    const __nv_bfloat16* gsrc2 = BhT + (size_t)(nbase + r) * DM + hf * 8;
    const __nv_bfloat16* gsrc3 = BlT + (size_t)(nbase + r) * DM + hf * 8;
    const uint32_t sdst = r * ROWB + hf * 16;

    // ldmatrix lane offsets
    const int wm = (warp >> 2) * 64, wn = (warp & 3) * 32;
    const int lrow = lane & 15, lcol = lane & 16;  // byte col 0 or 16
    uint32_t aoff[4], boff[2];
#pragma unroll
    for (int mt = 0; mt < 4; mt++) aoff[mt] = (wm + mt * 16 + lrow) * ROWB + lcol;
#pragma unroll
    for (int j = 0; j < 2; j++)    boff[j] = (wn + j * 16 + lrow) * ROWB + lcol;

    float acc[4][4][4];
#pragma unroll
    for (int a = 0; a < 4; a++)
#pragma unroll
        for (int b = 0; b < 4; b++)
#pragma unroll
            for (int c = 0; c < 4; c++) acc[a][b][c] = 0.0f;

    // Prologue: fill 3 stages (tiles 0..2)
#pragma unroll
    for (int t = 0; t < NSTAGE; t++) {
        const uint32_t st = sb + t * STAGEB;
        const int kc = t * 16;
        CP16(st + 0 * PLANEB + sdst, gsrc0 + kc);
        CP16(st + 1 * PLANEB + sdst, gsrc1 + kc);
        CP16(st + 2 * PLANEB + sdst, gsrc2 + kc);
        CP16(st + 3 * PLANEB + sdst, gsrc3 + kc);
        CP_COMMIT();
    }

    const int KT = DM / 16;  // 64
    for (int t = 0; t < KT; t++) {
        CP_WAIT2();
        __syncthreads();
        const uint32_t st = sb + (t % NSTAGE) * STAGEB;

        // Fragment loads (all smem reads for this tile)
        unsigned bh[4][2], bl[4][2];
#pragma unroll
        for (int j = 0; j < 2; j++) {
            unsigned r0, r1, r2, r3;
            LDSM4(r0, r1, r2, r3, st + 2 * PLANEB + boff[j]);
            bh[2 * j][0] = r0; bh[2 * j + 1][0] = r1;
            bh[2 * j][1] = r2; bh[2 * j + 1][1] = r3;
            LDSM4(r0, r1, r2, r3, st + 3 * PLANEB + boff[j]);
            bl[2 * j][0] = r0; bl[2 * j + 1][0] = r1;
            bl[2 * j][1] = r2; bl[2 * j + 1][1] = r3;
        }
        unsigned ah[4][4], al[4][4];
#pragma unroll
        for (int mt = 0; mt < 4; mt++) {
            LDSM4(ah[mt][0], ah[mt][1], ah[mt][2], ah[mt][3], st + 0 * PLANEB + aoff[mt]);
            LDSM4(al[mt][0], al[mt][1], al[mt][2], al[mt][3], st + 1 * PLANEB + aoff[mt]);
        }
        __syncthreads();  // all reads done; stage may be overwritten

        // Refill this stage with tile t+3
        if (t + NSTAGE < KT) {
            const int kc = (t + NSTAGE) * 16;
            CP16(st + 0 * PLANEB + sdst, gsrc0 + kc);
            CP16(st + 1 * PLANEB + sdst, gsrc1 + kc);
            CP16(st + 2 * PLANEB + sdst, gsrc2 + kc);
            CP16(st + 3 * PLANEB + sdst, gsrc3 + kc);
        }
        CP_COMMIT();

        // 48 HMMA: 3-pass bf16x2
#pragma unroll
        for (int mt = 0; mt < 4; mt++)
#pragma unroll
            for (int nt = 0; nt < 4; nt++) {
                mma_bf(acc[mt][nt], ah[mt], bh[nt]);
                mma_bf(acc[mt][nt], ah[mt], bl[nt]);
                mma_bf(acc[mt][nt], al[mt], bh[nt]);
            }
    }

    // Epilogue
    const int g = lane >> 2, tig = lane & 3;
#pragma unroll
    for (int mt = 0; mt < 4; mt++)
#pragma unroll
        for (int nt = 0; nt < 4; nt++) {
            int row = m0 + wm + mt * 16 + g;
            int cc = col0 + wn + nt * 8 + 2 * tig;
            *(float2*)(out + (size_t)row * DM + cc) =
                make_float2(acc[mt][nt][0], acc[mt][nt][1]);
            *(float2*)(out + (size_t)(row + 8) * DM + cc) =
                make_float2(acc[mt][nt][2], acc[mt][nt][3]);
        }
}

// ---------------------------------------------------------------------------
// Warp-tiled flash attention (proven R1 math); epilogue writes bf16 hi/lo
// planes feeding the final GEMM.
// ---------------------------------------------------------------------------
__global__ void __launch_bounds__(128) attn_kernel()
{
    __shared__ unsigned Qh[64][36], Ql[64][36];
    __shared__ unsigned Kh[32][36], Kl[32][36];
    __shared__ unsigned Vs[32][72];

    const int h = blockIdx.y, t0 = blockIdx.x * 64;
    const int tid = threadIdx.x;
    const int lane = tid & 31, warp = tid >> 5;
    const int g = lane >> 2, tig = lane & 3;
    const int wq = t0 + warp * 16;

#pragma unroll
    for (int u = 0; u < 8; u++) {
        int idx = tid + u * 128;
        int r = idx >> 4, kp = (idx & 15) * 2;
        float4 v = *(const float4*)(g_q + (size_t)(t0 + r) * DM + h * DH + kp * 2);
        unsigned h0, l0, h1, l1;
        split_pair(v.x * 0.125f, v.y * 0.125f, h0, l0);
        split_pair(v.z * 0.125f, v.w * 0.125f, h1, l1);
        Qh[r][kp] = h0; Ql[r][kp] = l0;
        Qh[r][kp + 1] = h1; Ql[r][kp + 1] = l1;
    }
    __syncthreads();

    unsigned qh[4][4], ql[4][4];
    const int rA = warp * 16 + g;
#pragma unroll
    for (int ks = 0; ks < 4; ks++) {
        qh[ks][0] = Qh[rA][ks * 8 + tig];     qh[ks][1] = Qh[rA + 8][ks * 8 + tig];
        qh[ks][2] = Qh[rA][ks * 8 + tig + 4]; qh[ks][3] = Qh[rA + 8][ks * 8 + tig + 4];
        ql[ks][0] = Ql[rA][ks * 8 + tig];     ql[ks][1] = Ql[rA + 8][ks * 8 + tig];
        ql[ks][2] = Ql[rA][ks * 8 + tig + 4]; ql[ks][3] = Ql[rA + 8][ks * 8 + tig + 4];
    }
    __syncwarp();

    float o[8][4];
#pragma unroll
    for (int nt = 0; nt < 8; nt++)
#pragma unroll
        for (int e = 0; e < 4; e++) o[nt][e] = 0.0f;
    float m0 = -1e30f, m1 = -1e30f, l0 = 0.0f, l1 = 0.0f;

    const int jlo = max(0, t0 - WIN);
    const int jtop_w = ((wq + 15) >> 5) << 5;

    for (int jc = t0 + 32; jc >= jlo; jc -= 32) {
        __syncthreads();
#pragma unroll
        for (int u = 0; u < 4; u++) {
            int idx = tid + u * 128;
            int r = idx >> 4, kp = (idx & 15) * 2;
            float4 kv = *(const float4*)(g_k + (size_t)(jc + r) * DM + h * DH + kp * 2);
            unsigned h0, lv0, h1, lv1;
            split_pair(kv.x, kv.y, h0, lv0);
            split_pair(kv.z, kv.w, h1, lv1);
            Kh[r][kp] = h0; Kl[r][kp] = lv0;
            Kh[r][kp + 1] = h1; Kl[r][kp + 1] = lv1;
            float4 vv = *(const float4*)(g_v + (size_t)(jc + r) * DM + h * DH + kp * 2);
            Vs[r][kp * 2 + 0] = f2tf(vv.x); Vs[r][kp * 2 + 1] = f2tf(vv.y);
            Vs[r][kp * 2 + 2] = f2tf(vv.z); Vs[r][kp * 2 + 3] = f2tf(vv.w);
        }
        __syncthreads();

        if (jc <= jtop_w && jc + 31 + WIN >= wq) {
            float s[4][4];
#pragma unroll
            for (int nt = 0; nt < 4; nt++)
#pragma unroll
                for (int e = 0; e < 4; e++) s[nt][e] = 0.0f;
#pragma unroll
            for (int ks = 0; ks < 4; ks++) {
#pragma unroll
                for (int nt = 0; nt < 4; nt++) {
                    unsigned bh[2], bl[2];
                    bh[0] = Kh[nt * 8 + g][ks * 8 + tig];
                    bh[1] = Kh[nt * 8 + g][ks * 8 + tig + 4];
                    bl[0] = Kl[nt * 8 + g][ks * 8 + tig];
                    bl[1] = Kl[nt * 8 + g][ks * 8 + tig + 4];
                    mma_bf(s[nt], qh[ks], bh);
                    mma_bf(s[nt], qh[ks], bl);
                    mma_bf(s[nt], ql[ks], bh);
                }
            }

            const int r0 = wq + g, r1 = r0 + 8;
            float mx0 = -1e30f, mx1 = -1e30f;
#pragma unroll
            for (int nt = 0; nt < 4; nt++) {
#pragma unroll
                for (int e = 0; e < 2; e++) {
                    int j = jc + nt * 8 + 2 * tig + e;
                    if (j > r0 || j + WIN < r0) s[nt][e] = -1e30f;
                    if (j > r1 || j + WIN < r1) s[nt][2 + e] = -1e30f;
                    mx0 = fmaxf(mx0, s[nt][e]);
                    mx1 = fmaxf(mx1, s[nt][2 + e]);
                }
            }
            mx0 = fmaxf(mx0, __shfl_xor_sync(0xffffffffu, mx0, 1));
            mx0 = fmaxf(mx0, __shfl_xor_sync(0xffffffffu, mx0, 2));
            mx1 = fmaxf(mx1, __shfl_xor_sync(0xffffffffu, mx1, 1));
            mx1 = fmaxf(mx1, __shfl_xor_sync(0xffffffffu, mx1, 2));
            float mn0 = fmaxf(m0, mx0), mn1 = fmaxf(m1, mx1);
            float c0 = __expf(m0 - mn0), c1 = __expf(m1 - mn1);
            m0 = mn0; m1 = mn1;
            l0 *= c0; l1 *= c1;
#pragma unroll
            for (int nt = 0; nt < 8; nt++) {
                o[nt][0] *= c0; o[nt][1] *= c0;
                o[nt][2] *= c1; o[nt][3] *= c1;
            }
            float ls0 = 0.0f, ls1 = 0.0f;
#pragma unroll
            for (int nt = 0; nt < 4; nt++) {
                float p00 = __expf(s[nt][0] - mn0), p01 = __expf(s[nt][1] - mn0);
                float p10 = __expf(s[nt][2] - mn1), p11 = __expf(s[nt][3] - mn1);
                ls0 += p00 + p01; ls1 += p10 + p11;
                uint2 w0; w0.x = f2tf(p00); w0.y = f2tf(p01);
                uint2 w1; w1.x = f2tf(p10); w1.y = f2tf(p11);
                *(uint2*)&Qh[rA][nt * 8 + 2 * tig] = w0;
                *(uint2*)&Qh[rA + 8][nt * 8 + 2 * tig] = w1;
            }
            ls0 += __shfl_xor_sync(0xffffffffu, ls0, 1);
            ls0 += __shfl_xor_sync(0xffffffffu, ls0, 2);
            ls1 += __shfl_xor_sync(0xffffffffu, ls1, 1);
            ls1 += __shfl_xor_sync(0xffffffffu, ls1, 2);
            l0 += ls0; l1 += ls1;
            __syncwarp();

#pragma unroll
            for (int ks2 = 0; ks2 < 4; ks2++) {
                unsigned pa[4];
                pa[0] = Qh[rA][ks2 * 8 + tig];
                pa[1] = Qh[rA + 8][ks2 * 8 + tig];
                pa[2] = Qh[rA][ks2 * 8 + tig + 4];
                pa[3] = Qh[rA + 8][ks2 * 8 + tig + 4];
#pragma unroll
                for (int nt = 0; nt < 8; nt++) {
                    unsigned vb[2];
                    vb[0] = Vs[ks2 * 8 + tig][nt * 8 + g];
                    vb[1] = Vs[ks2 * 8 + tig + 4][nt * 8 + g];
                    mma_tf(o[nt], pa, vb);
                }
            }
        }
    }

    // Epilogue: normalize + split to planes for the final GEMM
    const float inv0 = 1.0f / l0, inv1 = 1.0f / l1;
#pragma unroll
    for (int nt = 0; nt < 8; nt++) {
        int col = h * DH + nt * 8 + 2 * tig;
        unsigned hh, ll;
        split_pair(o[nt][0] * inv0, o[nt][1] * inv0, hh, ll);
        *(unsigned*)(g_ah + (size_t)(wq + g) * DM + col) = hh;
        *(unsigned*)(g_al + (size_t)(wq + g) * DM + col) = ll;
        split_pair(o[nt][2] * inv1, o[nt][3] * inv1, hh, ll);
        *(unsigned*)(g_ah + (size_t)(wq + g + 8) * DM + col) = hh;
        *(unsigned*)(g_al + (size_t)(wq + g + 8) * DM + col) = ll;
    }
}

// ---------------------------------------------------------------------------
extern "C" void kernel_launch(void* const* d_in, const int* in_sizes, int n_in,
                              void* d_out, int out_size)
{
    const float* x  = (const float*)d_in[0];
    const float* Wq = (const float*)d_in[1];
    const float* Wk = (const float*)d_in[2];
    const float* Wv = (const float*)d_in[3];
    const float* Wo = (const float*)d_in[4];
    float* out = (float*)d_out;

    float *q, *k, *v;
    __nv_bfloat16 *xh, *xl, *ah, *al, *wh, *wl;
    cudaGetSymbolAddress((void**)&q,  g_q);
    cudaGetSymbolAddress((void**)&k,  g_k);
    cudaGetSymbolAddress((void**)&v,  g_v);
    cudaGetSymbolAddress((void**)&xh, g_xh);
    cudaGetSymbolAddress((void**)&xl, g_xl);
    cudaGetSymbolAddress((void**)&ah, g_ah);
    cudaGetSymbolAddress((void**)&al, g_al);
    cudaGetSymbolAddress((void**)&wh, g_wh);
    cudaGetSymbolAddress((void**)&wl, g_wl);

    cudaFuncSetAttribute(gemm_planes, cudaFuncAttributeMaxDynamicSharedMemorySize, GSMEM);

    // One-time conversions
    dim3 tgrid(DM / 32, DM / 32), tblk(32, 8);
    tsplit<<<tgrid, tblk>>>(Wq, wh + 0 * DM * DM, wl + 0 * DM * DM);
    tsplit<<<tgrid, tblk>>>(Wk, wh + 1 * DM * DM, wl + 1 * DM * DM);
    tsplit<<<tgrid, tblk>>>(Wv, wh + 2 * DM * DM, wl + 2 * DM * DM);
    tsplit<<<tgrid, tblk>>>(Wo, wh + 3 * DM * DM, wl + 3 * DM * DM);
    split_plain<<<SEQ * DM / 1024, 256>>>(x, xh, xl);

    // Fused QKV GEMM: N = 3072 (Wq^T|Wk^T|Wv^T planes are contiguous)
    gemm_planes<<<dim3(24, SEQ / 128), 256, GSMEM>>>(xh, xl, wh, wl, q, k, v);

    attn_kernel<<<dim3(SEQ / 64, NH), 128>>>();

    // Output projection
    gemm_planes<<<dim3(8, SEQ / 128), 256, GSMEM>>>(
        ah, al, wh + 3 * DM * DM, wl + 3 * DM * DM, out, out, out);
}

// round 7
// speedup vs baseline: 1.0197x; 1.0197x over previous
#include <cuda_runtime.h>
#include <cuda_bf16.h>
#include <cstdint>

#define SEQ 4096
#define DM  1024
#define NH  16
#define DH  64
#define WIN 256

// ---------------------------------------------------------------------------
// Scratch (allocation-free rule)
// ---------------------------------------------------------------------------
__device__ float g_q[SEQ * DM];
__device__ float g_k[SEQ * DM];
__device__ float g_v[SEQ * DM];
__device__ __nv_bfloat16 g_xh[SEQ * DM], g_xl[SEQ * DM];      // x split planes
__device__ __nv_bfloat16 g_ah[SEQ * DM], g_al[SEQ * DM];      // attn-out planes
__device__ __nv_bfloat16 g_wh[4][DM * DM], g_wl[4][DM * DM];  // W^T planes (q,k,v,o)

// ---------------------------------------------------------------------------
// Helpers
// ---------------------------------------------------------------------------
__device__ __forceinline__ uint32_t smem_u32(const void* p) {
    uint32_t a;
    asm("{ .reg .u64 t; cvta.to.shared.u64 t, %1; cvt.u32.u64 %0, t; }" : "=r"(a) : "l"(p));
    return a;
}
__device__ __forceinline__ unsigned f2tf(float f) {
    unsigned r; asm("cvt.rna.tf32.f32 %0, %1;" : "=r"(r) : "f"(f)); return r;
}
__device__ __forceinline__ void split_pair(float x, float y, unsigned& hi, unsigned& lo) {
    __nv_bfloat16 hx = __float2bfloat16(x), hy = __float2bfloat16(y);
    __nv_bfloat16 lx = __float2bfloat16(x - __bfloat162float(hx));
    __nv_bfloat16 ly = __float2bfloat16(y - __bfloat162float(hy));
    __nv_bfloat162 h; h.x = hx; h.y = hy;
    __nv_bfloat162 l; l.x = lx; l.y = ly;
    hi = *(unsigned*)&h; lo = *(unsigned*)&l;
}
__device__ __forceinline__ void mma_bf(float* c, const unsigned* a, const unsigned* b) {
    asm volatile("mma.sync.aligned.m16n8k16.row.col.f32.bf16.bf16.f32 "
        "{%0,%1,%2,%3},{%4,%5,%6,%7},{%8,%9},{%0,%1,%2,%3};"
        : "+f"(c[0]), "+f"(c[1]), "+f"(c[2]), "+f"(c[3])
        : "r"(a[0]), "r"(a[1]), "r"(a[2]), "r"(a[3]), "r"(b[0]), "r"(b[1]));
}
__device__ __forceinline__ void mma_tf(float* c, const unsigned* a, const unsigned* b) {
    asm volatile("mma.sync.aligned.m16n8k8.row.col.f32.tf32.tf32.f32 "
        "{%0,%1,%2,%3},{%4,%5,%6,%7},{%8,%9},{%0,%1,%2,%3};"
        : "+f"(c[0]), "+f"(c[1]), "+f"(c[2]), "+f"(c[3])
        : "r"(a[0]), "r"(a[1]), "r"(a[2]), "r"(a[3]), "r"(b[0]), "r"(b[1]));
}
#define CP16(dst, src) \
    asm volatile("cp.async.cg.shared.global [%0], [%1], 16;" :: "r"(dst), "l"(src))
#define CP_COMMIT() asm volatile("cp.async.commit_group;" ::: "memory")
#define CP_WAIT3()  asm volatile("cp.async.wait_group 3;" ::: "memory")
#define LDSM4(r0, r1, r2, r3, a) \
    asm volatile("ldmatrix.sync.aligned.m8n8.x4.shared.b16 {%0,%1,%2,%3}, [%4];" \
        : "=r"(r0), "=r"(r1), "=r"(r2), "=r"(r3) : "r"(a))

// ---------------------------------------------------------------------------
// Conversion kernels (one-time per launch)
// ---------------------------------------------------------------------------
__global__ void split_plain(const float* __restrict__ src,
                            __nv_bfloat16* __restrict__ hi, __nv_bfloat16* __restrict__ lo) {
    int i = (blockIdx.x * blockDim.x + threadIdx.x) * 4;
    float4 v = *(const float4*)(src + i);
    unsigned h0, l0, h1, l1;
    split_pair(v.x, v.y, h0, l0);
    split_pair(v.z, v.w, h1, l1);
    *(uint2*)(hi + i) = make_uint2(h0, h1);
    *(uint2*)(lo + i) = make_uint2(l0, l1);
}

// All four W [K=DM][N=DM] -> hT/lT [N][K] bf16 planes, one launch (grid.z = 4)
__global__ void tsplit4(const float* __restrict__ W0, const float* __restrict__ W1,
                        const float* __restrict__ W2, const float* __restrict__ W3,
                        __nv_bfloat16* __restrict__ hT, __nv_bfloat16* __restrict__ lT) {
    __shared__ float tile[32][33];
    const int z = blockIdx.z;
    const float* W = z == 0 ? W0 : (z == 1 ? W1 : (z == 2 ? W2 : W3));
    __nv_bfloat16* h_out = hT + (size_t)z * DM * DM;
    __nv_bfloat16* l_out = lT + (size_t)z * DM * DM;
    int k0 = blockIdx.y * 32, n0 = blockIdx.x * 32;
    int tx = threadIdx.x, ty = threadIdx.y;
#pragma unroll
    for (int j = 0; j < 32; j += 8)
        tile[ty + j][tx] = W[(size_t)(k0 + ty + j) * DM + n0 + tx];
    __syncthreads();
#pragma unroll
    for (int j = 0; j < 32; j += 8) {
        float v = tile[tx][ty + j];
        __nv_bfloat16 h = __float2bfloat16(v);
        size_t o = (size_t)(n0 + ty + j) * DM + k0 + tx;
        h_out[o] = h;
        l_out[o] = __float2bfloat16(v - __bfloat162float(h));
    }
}

// ---------------------------------------------------------------------------
// Pipelined bf16x2 HMMA GEMM on precomputed planes.
// 256 threads (8 warps, 2x4), block tile 128x128, warp tile 64x32, BK=16,
// 4-stage cp.async ring. Smem rows 48B (conflict-free ldmatrix).
// Fragment liveness minimized: B frags resident (16 regs), A frags transient
// per-mt (8 regs) -> fits the 128-reg cap at 2 CTAs/SM without spills.
// ---------------------------------------------------------------------------
#define ROWB    48
#define PLANEB  (128 * ROWB)        // 6144
#define STAGEB  (4 * PLANEB)        // 24576
#define NSTAGE  4
#define GSMEM   (NSTAGE * STAGEB)   // 98304

__global__ void __launch_bounds__(256, 2) gemm_planes(
    const __nv_bfloat16* __restrict__ Ah, const __nv_bfloat16* __restrict__ Al,
    const __nv_bfloat16* __restrict__ BhT, const __nv_bfloat16* __restrict__ BlT,
    float* __restrict__ O0, float* __restrict__ O1, float* __restrict__ O2)
{
    extern __shared__ char dynsmem[];
    const uint32_t sb = smem_u32(dynsmem);
    const int tid = threadIdx.x, lane = tid & 31, warp = tid >> 5;
    const int m0 = blockIdx.y * 128;
    const int nb = blockIdx.x;
    const int nbase = nb * 128;
    float* out = (nb >> 3) == 0 ? O0 : ((nb >> 3) == 1 ? O1 : O2);
    const int col0 = (nb & 7) * 128;

    // cp.async task: thread -> (row r, 16B half hf) for each of the 4 planes
    const int r = tid >> 1, hf = tid & 1;
    const __nv_bfloat16* gsrc0 = Ah  + (size_t)(m0 + r) * DM + hf * 8;
    const __nv_bfloat16* gsrc1 = Al  + (size_t)(m0 + r) * DM + hf * 8;
    const __nv_bfloat16* gsrc2 = BhT + (size_t)(nbase + r) * DM + hf * 8;
    const __nv_bfloat16* gsrc3 = BlT + (size_t)(nbase + r) * DM + hf * 8;
    const uint32_t sdst = r * ROWB + hf * 16;

    // ldmatrix lane address bases (per-mt/per-j offsets are immediates)
    const int wm = (warp >> 2) * 64, wn = (warp & 3) * 32;
    const int lrow = lane & 15, lcol = lane & 16;  // byte col 0 or 16
    const uint32_t abase = (wm + lrow) * ROWB + lcol;   // + mt*16*ROWB
    const uint32_t bbase = (wn + lrow) * ROWB + lcol;   // + j*16*ROWB

    float acc[4][4][4];
#pragma unroll
    for (int a = 0; a < 4; a++)
#pragma unroll
        for (int b = 0; b < 4; b++)
#pragma unroll
            for (int c = 0; c < 4; c++) acc[a][b][c] = 0.0f;

    // Prologue: fill 4 stages (tiles 0..3)
#pragma unroll
    for (int t = 0; t < NSTAGE; t++) {
        const uint32_t st = sb + t * STAGEB;
        const int kc = t * 16;
        CP16(st + 0 * PLANEB + sdst, gsrc0 + kc);
        CP16(st + 1 * PLANEB + sdst, gsrc1 + kc);
        CP16(st + 2 * PLANEB + sdst, gsrc2 + kc);
        CP16(st + 3 * PLANEB + sdst, gsrc3 + kc);
        CP_COMMIT();
    }

    const int KT = DM / 16;  // 64
    for (int t = 0; t < KT; t++) {
        CP_WAIT3();
        __syncthreads();
        const uint32_t st = sb + (t % NSTAGE) * STAGEB;

        // B fragments (resident): 16 regs
        unsigned bh[4][2], bl[4][2];
#pragma unroll
        for (int j = 0; j < 2; j++) {
            unsigned r0, r1, r2, r3;
            LDSM4(r0, r1, r2, r3, st + 2 * PLANEB + bbase + j * (16 * ROWB));
            bh[2 * j][0] = r0; bh[2 * j + 1][0] = r1;
            bh[2 * j][1] = r2; bh[2 * j + 1][1] = r3;
            LDSM4(r0, r1, r2, r3, st + 3 * PLANEB + bbase + j * (16 * ROWB));
            bl[2 * j][0] = r0; bl[2 * j + 1][0] = r1;
            bl[2 * j][1] = r2; bl[2 * j + 1][1] = r3;
        }

        // A fragments transient per mt; consume immediately
#pragma unroll
        for (int mt = 0; mt < 4; mt++) {
            unsigned ah[4], al[4];
            LDSM4(ah[0], ah[1], ah[2], ah[3], st + 0 * PLANEB + abase + mt * (16 * ROWB));
            LDSM4(al[0], al[1], al[2], al[3], st + 1 * PLANEB + abase + mt * (16 * ROWB));
#pragma unroll
            for (int nt = 0; nt < 4; nt++) {
                mma_bf(acc[mt][nt], ah, bh[nt]);
                mma_bf(acc[mt][nt], ah, bl[nt]);
                mma_bf(acc[mt][nt], al, bh[nt]);
            }
        }
        __syncthreads();  // all smem reads done; stage may be overwritten

        // Refill this stage with tile t+NSTAGE
        if (t + NSTAGE < KT) {
            const int kc = (t + NSTAGE) * 16;
            CP16(st + 0 * PLANEB + sdst, gsrc0 + kc);
            CP16(st + 1 * PLANEB + sdst, gsrc1 + kc);
            CP16(st + 2 * PLANEB + sdst, gsrc2 + kc);
            CP16(st + 3 * PLANEB + sdst, gsrc3 + kc);
        }
        CP_COMMIT();
    }

    // Epilogue
    const int g = lane >> 2, tig = lane & 3;
#pragma unroll
    for (int mt = 0; mt < 4; mt++)
#pragma unroll
        for (int nt = 0; nt < 4; nt++) {
            int row = m0 + wm + mt * 16 + g;
            int cc = col0 + wn + nt * 8 + 2 * tig;
            *(float2*)(out + (size_t)row * DM + cc) =
                make_float2(acc[mt][nt][0], acc[mt][nt][1]);
            *(float2*)(out + (size_t)(row + 8) * DM + cc) =
                make_float2(acc[mt][nt][2], acc[mt][nt][3]);
        }
}

// ---------------------------------------------------------------------------
// Warp-tiled flash attention (proven math, unchanged); epilogue emits bf16
// hi/lo planes feeding the final GEMM.
// ---------------------------------------------------------------------------
__global__ void __launch_bounds__(128) attn_kernel()
{
    __shared__ unsigned Qh[64][36], Ql[64][36];
    __shared__ unsigned Kh[32][36], Kl[32][36];
    __shared__ unsigned Vs[32][72];

    const int h = blockIdx.y, t0 = blockIdx.x * 64;
    const int tid = threadIdx.x;
    const int lane = tid & 31, warp = tid >> 5;
    const int g = lane >> 2, tig = lane & 3;
    const int wq = t0 + warp * 16;

#pragma unroll
    for (int u = 0; u < 8; u++) {
        int idx = tid + u * 128;
        int r = idx >> 4, kp = (idx & 15) * 2;
        float4 v = *(const float4*)(g_q + (size_t)(t0 + r) * DM + h * DH + kp * 2);
        unsigned h0, l0, h1, l1;
        split_pair(v.x * 0.125f, v.y * 0.125f, h0, l0);
        split_pair(v.z * 0.125f, v.w * 0.125f, h1, l1);
        Qh[r][kp] = h0; Ql[r][kp] = l0;
        Qh[r][kp + 1] = h1; Ql[r][kp + 1] = l1;
    }
    __syncthreads();

    unsigned qh[4][4], ql[4][4];
    const int rA = warp * 16 + g;
#pragma unroll
    for (int ks = 0; ks < 4; ks++) {
        qh[ks][0] = Qh[rA][ks * 8 + tig];     qh[ks][1] = Qh[rA + 8][ks * 8 + tig];
        qh[ks][2] = Qh[rA][ks * 8 + tig + 4]; qh[ks][3] = Qh[rA + 8][ks * 8 + tig + 4];
        ql[ks][0] = Ql[rA][ks * 8 + tig];     ql[ks][1] = Ql[rA + 8][ks * 8 + tig];
        ql[ks][2] = Ql[rA][ks * 8 + tig + 4]; ql[ks][3] = Ql[rA + 8][ks * 8 + tig + 4];
    }
    __syncwarp();

    float o[8][4];
#pragma unroll
    for (int nt = 0; nt < 8; nt++)
#pragma unroll
        for (int e = 0; e < 4; e++) o[nt][e] = 0.0f;
    float m0 = -1e30f, m1 = -1e30f, l0 = 0.0f, l1 = 0.0f;

    const int jlo = max(0, t0 - WIN);
    const int jtop_w = ((wq + 15) >> 5) << 5;

    for (int jc = t0 + 32; jc >= jlo; jc -= 32) {
        __syncthreads();
#pragma unroll
        for (int u = 0; u < 4; u++) {
            int idx = tid + u * 128;
            int r = idx >> 4, kp = (idx & 15) * 2;
            float4 kv = *(const float4*)(g_k + (size_t)(jc + r) * DM + h * DH + kp * 2);
            unsigned h0, lv0, h1, lv1;
            split_pair(kv.x, kv.y, h0, lv0);
            split_pair(kv.z, kv.w, h1, lv1);
            Kh[r][kp] = h0; Kl[r][kp] = lv0;
            Kh[r][kp + 1] = h1; Kl[r][kp + 1] = lv1;
            float4 vv = *(const float4*)(g_v + (size_t)(jc + r) * DM + h * DH + kp * 2);
            Vs[r][kp * 2 + 0] = f2tf(vv.x); Vs[r][kp * 2 + 1] = f2tf(vv.y);
            Vs[r][kp * 2 + 2] = f2tf(vv.z); Vs[r][kp * 2 + 3] = f2tf(vv.w);
        }
        __syncthreads();

        if (jc <= jtop_w && jc + 31 + WIN >= wq) {
            float s[4][4];
#pragma unroll
            for (int nt = 0; nt < 4; nt++)
#pragma unroll
                for (int e = 0; e < 4; e++) s[nt][e] = 0.0f;
#pragma unroll
            for (int ks = 0; ks < 4; ks++) {
#pragma unroll
                for (int nt = 0; nt < 4; nt++) {
                    unsigned bh[2], bl[2];
                    bh[0] = Kh[nt * 8 + g][ks * 8 + tig];
                    bh[1] = Kh[nt * 8 + g][ks * 8 + tig + 4];
                    bl[0] = Kl[nt * 8 + g][ks * 8 + tig];
                    bl[1] = Kl[nt * 8 + g][ks * 8 + tig + 4];
                    mma_bf(s[nt], qh[ks], bh);
                    mma_bf(s[nt], qh[ks], bl);
                    mma_bf(s[nt], ql[ks], bh);
                }
            }

            const int r0 = wq + g, r1 = r0 + 8;
            float mx0 = -1e30f, mx1 = -1e30f;
#pragma unroll
            for (int nt = 0; nt < 4; nt++) {
#pragma unroll
                for (int e = 0; e < 2; e++) {
                    int j = jc + nt * 8 + 2 * tig + e;
                    if (j > r0 || j + WIN < r0) s[nt][e] = -1e30f;
                    if (j > r1 || j + WIN < r1) s[nt][2 + e] = -1e30f;
                    mx0 = fmaxf(mx0, s[nt][e]);
                    mx1 = fmaxf(mx1, s[nt][2 + e]);
                }
            }
            mx0 = fmaxf(mx0, __shfl_xor_sync(0xffffffffu, mx0, 1));
            mx0 = fmaxf(mx0, __shfl_xor_sync(0xffffffffu, mx0, 2));
            mx1 = fmaxf(mx1, __shfl_xor_sync(0xffffffffu, mx1, 1));
            mx1 = fmaxf(mx1, __shfl_xor_sync(0xffffffffu, mx1, 2));
            float mn0 = fmaxf(m0, mx0), mn1 = fmaxf(m1, mx1);
            float c0 = __expf(m0 - mn0), c1 = __expf(m1 - mn1);
            m0 = mn0; m1 = mn1;
            l0 *= c0; l1 *= c1;
#pragma unroll
            for (int nt = 0; nt < 8; nt++) {
                o[nt][0] *= c0; o[nt][1] *= c0;
                o[nt][2] *= c1; o[nt][3] *= c1;
            }
            float ls0 = 0.0f, ls1 = 0.0f;
#pragma unroll
            for (int nt = 0; nt < 4; nt++) {
                float p00 = __expf(s[nt][0] - mn0), p01 = __expf(s[nt][1] - mn0);
                float p10 = __expf(s[nt][2] - mn1), p11 = __expf(s[nt][3] - mn1);
                ls0 += p00 + p01; ls1 += p10 + p11;
                uint2 w0; w0.x = f2tf(p00); w0.y = f2tf(p01);
                uint2 w1; w1.x = f2tf(p10); w1.y = f2tf(p11);
                *(uint2*)&Qh[rA][nt * 8 + 2 * tig] = w0;
                *(uint2*)&Qh[rA + 8][nt * 8 + 2 * tig] = w1;
            }
            ls0 += __shfl_xor_sync(0xffffffffu, ls0, 1);
            ls0 += __shfl_xor_sync(0xffffffffu, ls0, 2);
            ls1 += __shfl_xor_sync(0xffffffffu, ls1, 1);
            ls1 += __shfl_xor_sync(0xffffffffu, ls1, 2);
            l0 += ls0; l1 += ls1;
            __syncwarp();

#pragma unroll
            for (int ks2 = 0; ks2 < 4; ks2++) {
                unsigned pa[4];
                pa[0] = Qh[rA][ks2 * 8 + tig];
                pa[1] = Qh[rA + 8][ks2 * 8 + tig];
                pa[2] = Qh[rA][ks2 * 8 + tig + 4];
                pa[3] = Qh[rA + 8][ks2 * 8 + tig + 4];
#pragma unroll
                for (int nt = 0; nt < 8; nt++) {
                    unsigned vb[2];
                    vb[0] = Vs[ks2 * 8 + tig][nt * 8 + g];
                    vb[1] = Vs[ks2 * 8 + tig + 4][nt * 8 + g];
                    mma_tf(o[nt], pa, vb);
                }
            }
        }
    }

    // Epilogue: normalize + split to planes for the final GEMM
    const float inv0 = 1.0f / l0, inv1 = 1.0f / l1;
#pragma unroll
    for (int nt = 0; nt < 8; nt++) {
        int col = h * DH + nt * 8 + 2 * tig;
        unsigned hh, ll;
        split_pair(o[nt][0] * inv0, o[nt][1] * inv0, hh, ll);
        *(unsigned*)(g_ah + (size_t)(wq + g) * DM + col) = hh;
        *(unsigned*)(g_al + (size_t)(wq + g) * DM + col) = ll;
        split_pair(o[nt][2] * inv1, o[nt][3] * inv1, hh, ll);
        *(unsigned*)(g_ah + (size_t)(wq + g + 8) * DM + col) = hh;
        *(unsigned*)(g_al + (size_t)(wq + g + 8) * DM + col) = ll;
    }
}

// ---------------------------------------------------------------------------
extern "C" void kernel_launch(void* const* d_in, const int* in_sizes, int n_in,
                              void* d_out, int out_size)
{
    const float* x  = (const float*)d_in[0];
    const float* Wq = (const float*)d_in[1];
    const float* Wk = (const float*)d_in[2];
    const float* Wv = (const float*)d_in[3];
    const float* Wo = (const float*)d_in[4];
    float* out = (float*)d_out;

    float *q, *k, *v;
    __nv_bfloat16 *xh, *xl, *ah, *al, *wh, *wl;
    cudaGetSymbolAddress((void**)&q,  g_q);
    cudaGetSymbolAddress((void**)&k,  g_k);
    cudaGetSymbolAddress((void**)&v,  g_v);
    cudaGetSymbolAddress((void**)&xh, g_xh);
    cudaGetSymbolAddress((void**)&xl, g_xl);
    cudaGetSymbolAddress((void**)&ah, g_ah);
    cudaGetSymbolAddress((void**)&al, g_al);
    cudaGetSymbolAddress((void**)&wh, g_wh);
    cudaGetSymbolAddress((void**)&wl, g_wl);

    cudaFuncSetAttribute(gemm_planes, cudaFuncAttributeMaxDynamicSharedMemorySize, GSMEM);

    // One-time conversions
    tsplit4<<<dim3(DM / 32, DM / 32, 4), dim3(32, 8)>>>(Wq, Wk, Wv, Wo, wh, wl);
    split_plain<<<SEQ * DM / 1024, 256>>>(x, xh, xl);

    // Fused QKV GEMM: N = 3072 (Wq^T|Wk^T|Wv^T planes are contiguous)
    gemm_planes<<<dim3(24, SEQ / 128), 256, GSMEM>>>(
        xh, xl, wh + 0 * (size_t)DM * DM, wl + 0 * (size_t)DM * DM, q, k, v);

    attn_kernel<<<dim3(SEQ / 64, NH), 128>>>();

    // Output projection
    gemm_planes<<<dim3(8, SEQ / 128), 256, GSMEM>>>(
        ah, al, wh + 3 * (size_t)DM * DM, wl + 3 * (size_t)DM * DM, out, out, out);
}

// round 8
// speedup vs baseline: 2.2169x; 2.1741x over previous
#include <cuda_runtime.h>
#include <cuda_bf16.h>
#include <cuda_fp16.h>
#include <cstdint>

#define SEQ 4096
#define DM  1024
#define NH  16
#define DH  64
#define WIN 256

// ---------------------------------------------------------------------------
// Scratch (allocation-free rule)
// ---------------------------------------------------------------------------
__device__ float g_q[SEQ * DM];
__device__ float g_k[SEQ * DM];
__device__ float g_v[SEQ * DM];
__device__ __half g_xh[SEQ * DM];            // x as fp16
__device__ __half g_ao[SEQ * DM];            // attention output as fp16
__device__ __half g_wt[4][DM * DM];          // W^T as fp16 (q,k,v,o)

// ---------------------------------------------------------------------------
// Helpers
// ---------------------------------------------------------------------------
__device__ __forceinline__ uint32_t smem_u32(const void* p) {
    uint32_t a;
    asm("{ .reg .u64 t; cvta.to.shared.u64 t, %1; cvt.u32.u64 %0, t; }" : "=r"(a) : "l"(p));
    return a;
}
__device__ __forceinline__ unsigned f2tf(float f) {
    unsigned r; asm("cvt.rna.tf32.f32 %0, %1;" : "=r"(r) : "f"(f)); return r;
}
__device__ __forceinline__ void split_pair(float x, float y, unsigned& hi, unsigned& lo) {
    __nv_bfloat16 hx = __float2bfloat16(x), hy = __float2bfloat16(y);
    __nv_bfloat16 lx = __float2bfloat16(x - __bfloat162float(hx));
    __nv_bfloat16 ly = __float2bfloat16(y - __bfloat162float(hy));
    __nv_bfloat162 h; h.x = hx; h.y = hy;
    __nv_bfloat162 l; l.x = lx; l.y = ly;
    hi = *(unsigned*)&h; lo = *(unsigned*)&l;
}
// bf16 MMA (attention QK^T path)
__device__ __forceinline__ void mma_bf(float* c, const unsigned* a, const unsigned* b) {
    asm volatile("mma.sync.aligned.m16n8k16.row.col.f32.bf16.bf16.f32 "
        "{%0,%1,%2,%3},{%4,%5,%6,%7},{%8,%9},{%0,%1,%2,%3};"
        : "+f"(c[0]), "+f"(c[1]), "+f"(c[2]), "+f"(c[3])
        : "r"(a[0]), "r"(a[1]), "r"(a[2]), "r"(a[3]), "r"(b[0]), "r"(b[1]));
}
// fp16 MMA (GEMM path)
__device__ __forceinline__ void mma_fp(float* c, const unsigned* a, const unsigned* b) {
    asm volatile("mma.sync.aligned.m16n8k16.row.col.f32.f16.f16.f32 "
        "{%0,%1,%2,%3},{%4,%5,%6,%7},{%8,%9},{%0,%1,%2,%3};"
        : "+f"(c[0]), "+f"(c[1]), "+f"(c[2]), "+f"(c[3])
        : "r"(a[0]), "r"(a[1]), "r"(a[2]), "r"(a[3]), "r"(b[0]), "r"(b[1]));
}
__device__ __forceinline__ void mma_tf(float* c, const unsigned* a, const unsigned* b) {
    asm volatile("mma.sync.aligned.m16n8k8.row.col.f32.tf32.tf32.f32 "
        "{%0,%1,%2,%3},{%4,%5,%6,%7},{%8,%9},{%0,%1,%2,%3};"
        : "+f"(c[0]), "+f"(c[1]), "+f"(c[2]), "+f"(c[3])
        : "r"(a[0]), "r"(a[1]), "r"(a[2]), "r"(a[3]), "r"(b[0]), "r"(b[1]));
}
#define CP16(dst, src) \
    asm volatile("cp.async.cg.shared.global [%0], [%1], 16;" :: "r"(dst), "l"(src))
#define CP_COMMIT() asm volatile("cp.async.commit_group;" ::: "memory")
#define CP_WAIT3()  asm volatile("cp.async.wait_group 3;" ::: "memory")
#define LDSM4(r0, r1, r2, r3, a) \
    asm volatile("ldmatrix.sync.aligned.m8n8.x4.shared.b16 {%0,%1,%2,%3}, [%4];" \
        : "=r"(r0), "=r"(r1), "=r"(r2), "=r"(r3) : "r"(a))

// ---------------------------------------------------------------------------
// Conversion kernels (one-time per launch)
// ---------------------------------------------------------------------------
__global__ void tohalf(const float* __restrict__ src, __half* __restrict__ dst) {
    int i = (blockIdx.x * blockDim.x + threadIdx.x) * 4;
    float4 v = *(const float4*)(src + i);
    __half2 a = __floats2half2_rn(v.x, v.y);
    __half2 b = __floats2half2_rn(v.z, v.w);
    *(uint2*)(dst + i) = make_uint2(*(unsigned*)&a, *(unsigned*)&b);
}

// All four W [K=DM][N=DM] -> W^T [N][K] fp16, one launch (grid.z = 4)
__global__ void tsplit4h(const float* __restrict__ W0, const float* __restrict__ W1,
                         const float* __restrict__ W2, const float* __restrict__ W3,
                         __half* __restrict__ T) {
    __shared__ float tile[32][33];
    const int z = blockIdx.z;
    const float* W = z == 0 ? W0 : (z == 1 ? W1 : (z == 2 ? W2 : W3));
    __half* t_out = T + (size_t)z * DM * DM;
    int k0 = blockIdx.y * 32, n0 = blockIdx.x * 32;
    int tx = threadIdx.x, ty = threadIdx.y;
#pragma unroll
    for (int j = 0; j < 32; j += 8)
        tile[ty + j][tx] = W[(size_t)(k0 + ty + j) * DM + n0 + tx];
    __syncthreads();
#pragma unroll
    for (int j = 0; j < 32; j += 8)
        t_out[(size_t)(n0 + ty + j) * DM + k0 + tx] = __float2half(tile[tx][ty + j]);
}

// ---------------------------------------------------------------------------
// Pipelined 1-pass fp16 HMMA GEMM.
// 256 threads (8 warps, 2x4), block tile 128x128, warp tile 64x32, BK=16,
// 4-stage cp.async ring, 2 planes (A rows, B^T rows), 48B smem row pitch.
// 16 MMA + 6 ldmatrix.x4 per warp per k-tile.
// ---------------------------------------------------------------------------
#define ROWB    48
#define PLANEB  (128 * ROWB)        // 6144
#define STAGEB  (2 * PLANEB)        // 12288
#define NSTAGE  4
#define GSMEM   (NSTAGE * STAGEB)   // 49152

__global__ void __launch_bounds__(256, 2) gemm_fp16(
    const __half* __restrict__ A, const __half* __restrict__ BT,
    float* __restrict__ O0, float* __restrict__ O1, float* __restrict__ O2)
{
    extern __shared__ char dynsmem[];
    const uint32_t sb = smem_u32(dynsmem);
    const int tid = threadIdx.x, lane = tid & 31, warp = tid >> 5;
    const int m0 = blockIdx.y * 128;
    const int nb = blockIdx.x;
    const int nbase = nb * 128;
    float* out = (nb >> 3) == 0 ? O0 : ((nb >> 3) == 1 ? O1 : O2);
    const int col0 = (nb & 7) * 128;

    // cp.async task: thread -> (row r, 16B half hf) for A and B planes
    const int r = tid >> 1, hf = tid & 1;
    const __half* gsrcA = A  + (size_t)(m0 + r) * DM + hf * 8;
    const __half* gsrcB = BT + (size_t)(nbase + r) * DM + hf * 8;
    const uint32_t sdst = r * ROWB + hf * 16;

    const int wm = (warp >> 2) * 64, wn = (warp & 3) * 32;
    const int lrow = lane & 15, lcol = lane & 16;
    const uint32_t abase = (wm + lrow) * ROWB + lcol;   // + mt*16*ROWB
    const uint32_t bbase = (wn + lrow) * ROWB + lcol;   // + j*16*ROWB

    float acc[4][4][4];
#pragma unroll
    for (int a = 0; a < 4; a++)
#pragma unroll
        for (int b = 0; b < 4; b++)
#pragma unroll
            for (int c = 0; c < 4; c++) acc[a][b][c] = 0.0f;

    // Prologue: fill 4 stages (tiles 0..3)
#pragma unroll
    for (int t = 0; t < NSTAGE; t++) {
        const uint32_t st = sb + t * STAGEB;
        const int kc = t * 16;
        CP16(st + sdst,          gsrcA + kc);
        CP16(st + PLANEB + sdst, gsrcB + kc);
        CP_COMMIT();
    }

    const int KT = DM / 16;  // 64
    for (int t = 0; t < KT; t++) {
        CP_WAIT3();
        __syncthreads();
        const uint32_t st = sb + (t % NSTAGE) * STAGEB;

        // B fragments resident (8 regs)
        unsigned bf[4][2];
#pragma unroll
        for (int j = 0; j < 2; j++) {
            unsigned r0, r1, r2, r3;
            LDSM4(r0, r1, r2, r3, st + PLANEB + bbase + j * (16 * ROWB));
            bf[2 * j][0] = r0; bf[2 * j + 1][0] = r1;
            bf[2 * j][1] = r2; bf[2 * j + 1][1] = r3;
        }
        // A fragments transient per mt
#pragma unroll
        for (int mt = 0; mt < 4; mt++) {
            unsigned af[4];
            LDSM4(af[0], af[1], af[2], af[3], st + abase + mt * (16 * ROWB));
#pragma unroll
            for (int nt = 0; nt < 4; nt++)
                mma_fp(acc[mt][nt], af, bf[nt]);
        }
        __syncthreads();

        if (t + NSTAGE < KT) {
            const int kc = (t + NSTAGE) * 16;
            CP16(st + sdst,          gsrcA + kc);
            CP16(st + PLANEB + sdst, gsrcB + kc);
        }
        CP_COMMIT();
    }

    // Epilogue
    const int g = lane >> 2, tig = lane & 3;
#pragma unroll
    for (int mt = 0; mt < 4; mt++)
#pragma unroll
        for (int nt = 0; nt < 4; nt++) {
            int row = m0 + wm + mt * 16 + g;
            int cc = col0 + wn + nt * 8 + 2 * tig;
            *(float2*)(out + (size_t)row * DM + cc) =
                make_float2(acc[mt][nt][0], acc[mt][nt][1]);
            *(float2*)(out + (size_t)(row + 8) * DM + cc) =
                make_float2(acc[mt][nt][2], acc[mt][nt][3]);
        }
}

// ---------------------------------------------------------------------------
// Warp-tiled flash attention — math identical to the 2.737e-4 runs.
// Epilogue writes fp16 (g_ao) feeding the O-projection GEMM.
// ---------------------------------------------------------------------------
__global__ void __launch_bounds__(128) attn_kernel()
{
    __shared__ unsigned Qh[64][36], Ql[64][36];
    __shared__ unsigned Kh[32][36], Kl[32][36];
    __shared__ unsigned Vs[32][72];

    const int h = blockIdx.y, t0 = blockIdx.x * 64;
    const int tid = threadIdx.x;
    const int lane = tid & 31, warp = tid >> 5;
    const int g = lane >> 2, tig = lane & 3;
    const int wq = t0 + warp * 16;

#pragma unroll
    for (int u = 0; u < 8; u++) {
        int idx = tid + u * 128;
        int r = idx >> 4, kp = (idx & 15) * 2;
        float4 v = *(const float4*)(g_q + (size_t)(t0 + r) * DM + h * DH + kp * 2);
        unsigned h0, l0, h1, l1;
        split_pair(v.x * 0.125f, v.y * 0.125f, h0, l0);
        split_pair(v.z * 0.125f, v.w * 0.125f, h1, l1);
        Qh[r][kp] = h0; Ql[r][kp] = l0;
        Qh[r][kp + 1] = h1; Ql[r][kp + 1] = l1;
    }
    __syncthreads();

    unsigned qh[4][4], ql[4][4];
    const int rA = warp * 16 + g;
#pragma unroll
    for (int ks = 0; ks < 4; ks++) {
        qh[ks][0] = Qh[rA][ks * 8 + tig];     qh[ks][1] = Qh[rA + 8][ks * 8 + tig];
        qh[ks][2] = Qh[rA][ks * 8 + tig + 4]; qh[ks][3] = Qh[rA + 8][ks * 8 + tig + 4];
        ql[ks][0] = Ql[rA][ks * 8 + tig];     ql[ks][1] = Ql[rA + 8][ks * 8 + tig];
        ql[ks][2] = Ql[rA][ks * 8 + tig + 4]; ql[ks][3] = Ql[rA + 8][ks * 8 + tig + 4];
    }
    __syncwarp();

    float o[8][4];
#pragma unroll
    for (int nt = 0; nt < 8; nt++)
#pragma unroll
        for (int e = 0; e < 4; e++) o[nt][e] = 0.0f;
    float m0 = -1e30f, m1 = -1e30f, l0 = 0.0f, l1 = 0.0f;

    const int jlo = max(0, t0 - WIN);
    const int jtop_w = ((wq + 15) >> 5) << 5;

    for (int jc = t0 + 32; jc >= jlo; jc -= 32) {
        __syncthreads();
#pragma unroll
        for (int u = 0; u < 4; u++) {
            int idx = tid + u * 128;
            int r = idx >> 4, kp = (idx & 15) * 2;
            float4 kv = *(const float4*)(g_k + (size_t)(jc + r) * DM + h * DH + kp * 2);
            unsigned h0, lv0, h1, lv1;
            split_pair(kv.x, kv.y, h0, lv0);
            split_pair(kv.z, kv.w, h1, lv1);
            Kh[r][kp] = h0; Kl[r][kp] = lv0;
            Kh[r][kp + 1] = h1; Kl[r][kp + 1] = lv1;
            float4 vv = *(const float4*)(g_v + (size_t)(jc + r) * DM + h * DH + kp * 2);
            Vs[r][kp * 2 + 0] = f2tf(vv.x); Vs[r][kp * 2 + 1] = f2tf(vv.y);
            Vs[r][kp * 2 + 2] = f2tf(vv.z); Vs[r][kp * 2 + 3] = f2tf(vv.w);
        }
        __syncthreads();

        if (jc <= jtop_w && jc + 31 + WIN >= wq) {
            float s[4][4];
#pragma unroll
            for (int nt = 0; nt < 4; nt++)
#pragma unroll
                for (int e = 0; e < 4; e++) s[nt][e] = 0.0f;
#pragma unroll
            for (int ks = 0; ks < 4; ks++) {
#pragma unroll
                for (int nt = 0; nt < 4; nt++) {
                    unsigned bh[2], bl[2];
                    bh[0] = Kh[nt * 8 + g][ks * 8 + tig];
                    bh[1] = Kh[nt * 8 + g][ks * 8 + tig + 4];
                    bl[0] = Kl[nt * 8 + g][ks * 8 + tig];
                    bl[1] = Kl[nt * 8 + g][ks * 8 + tig + 4];
                    mma_bf(s[nt], qh[ks], bh);
                    mma_bf(s[nt], qh[ks], bl);
                    mma_bf(s[nt], ql[ks], bh);
                }
            }

            const int r0 = wq + g, r1 = r0 + 8;
            float mx0 = -1e30f, mx1 = -1e30f;
#pragma unroll
            for (int nt = 0; nt < 4; nt++) {
#pragma unroll
                for (int e = 0; e < 2; e++) {
                    int j = jc + nt * 8 + 2 * tig + e;
                    if (j > r0 || j + WIN < r0) s[nt][e] = -1e30f;
                    if (j > r1 || j + WIN < r1) s[nt][2 + e] = -1e30f;
                    mx0 = fmaxf(mx0, s[nt][e]);
                    mx1 = fmaxf(mx1, s[nt][2 + e]);
                }
            }
            mx0 = fmaxf(mx0, __shfl_xor_sync(0xffffffffu, mx0, 1));
            mx0 = fmaxf(mx0, __shfl_xor_sync(0xffffffffu, mx0, 2));
            mx1 = fmaxf(mx1, __shfl_xor_sync(0xffffffffu, mx1, 1));
            mx1 = fmaxf(mx1, __shfl_xor_sync(0xffffffffu, mx1, 2));
            float mn0 = fmaxf(m0, mx0), mn1 = fmaxf(m1, mx1);
            float c0 = __expf(m0 - mn0), c1 = __expf(m1 - mn1);
            m0 = mn0; m1 = mn1;
            l0 *= c0; l1 *= c1;
#pragma unroll
            for (int nt = 0; nt < 8; nt++) {
                o[nt][0] *= c0; o[nt][1] *= c0;
                o[nt][2] *= c1; o[nt][3] *= c1;
            }
            float ls0 = 0.0f, ls1 = 0.0f;
#pragma unroll
            for (int nt = 0; nt < 4; nt++) {
                float p00 = __expf(s[nt][0] - mn0), p01 = __expf(s[nt][1] - mn0);
                float p10 = __expf(s[nt][2] - mn1), p11 = __expf(s[nt][3] - mn1);
                ls0 += p00 + p01; ls1 += p10 + p11;
                uint2 w0; w0.x = f2tf(p00); w0.y = f2tf(p01);
                uint2 w1; w1.x = f2tf(p10); w1.y = f2tf(p11);
                *(uint2*)&Qh[rA][nt * 8 + 2 * tig] = w0;
                *(uint2*)&Qh[rA + 8][nt * 8 + 2 * tig] = w1;
            }
            ls0 += __shfl_xor_sync(0xffffffffu, ls0, 1);
            ls0 += __shfl_xor_sync(0xffffffffu, ls0, 2);
            ls1 += __shfl_xor_sync(0xffffffffu, ls1, 1);
            ls1 += __shfl_xor_sync(0xffffffffu, ls1, 2);
            l0 += ls0; l1 += ls1;
            __syncwarp();

#pragma unroll
            for (int ks2 = 0; ks2 < 4; ks2++) {
                unsigned pa[4];
                pa[0] = Qh[rA][ks2 * 8 + tig];
                pa[1] = Qh[rA + 8][ks2 * 8 + tig];
                pa[2] = Qh[rA][ks2 * 8 + tig + 4];
                pa[3] = Qh[rA + 8][ks2 * 8 + tig + 4];
#pragma unroll
                for (int nt = 0; nt < 8; nt++) {
                    unsigned vb[2];
                    vb[0] = Vs[ks2 * 8 + tig][nt * 8 + g];
                    vb[1] = Vs[ks2 * 8 + tig + 4][nt * 8 + g];
                    mma_tf(o[nt], pa, vb);
                }
            }
        }
    }

    // Epilogue: normalize + fp16 for the O-projection GEMM
    const float inv0 = 1.0f / l0, inv1 = 1.0f / l1;
#pragma unroll
    for (int nt = 0; nt < 8; nt++) {
        int col = h * DH + nt * 8 + 2 * tig;
        __half2 a = __floats2half2_rn(o[nt][0] * inv0, o[nt][1] * inv0);
        __half2 b = __floats2half2_rn(o[nt][2] * inv1, o[nt][3] * inv1);
        *(unsigned*)(g_ao + (size_t)(wq + g) * DM + col) = *(unsigned*)&a;
        *(unsigned*)(g_ao + (size_t)(wq + g + 8) * DM + col) = *(unsigned*)&b;
    }
}

// ---------------------------------------------------------------------------
extern "C" void kernel_launch(void* const* d_in, const int* in_sizes, int n_in,
                              void* d_out, int out_size)
{
    const float* x  = (const float*)d_in[0];
    const float* Wq = (const float*)d_in[1];
    const float* Wk = (const float*)d_in[2];
    const float* Wv = (const float*)d_in[3];
    const float* Wo = (const float*)d_in[4];
    float* out = (float*)d_out;

    float *q, *k, *v;
    __half *xh, *ao, *wt;
    cudaGetSymbolAddress((void**)&q,  g_q);
    cudaGetSymbolAddress((void**)&k,  g_k);
    cudaGetSymbolAddress((void**)&v,  g_v);
    cudaGetSymbolAddress((void**)&xh, g_xh);
    cudaGetSymbolAddress((void**)&ao, g_ao);
    cudaGetSymbolAddress((void**)&wt, g_wt);

    cudaFuncSetAttribute(gemm_fp16, cudaFuncAttributeMaxDynamicSharedMemorySize, GSMEM);

    // One-time conversions
    tsplit4h<<<dim3(DM / 32, DM / 32, 4), dim3(32, 8)>>>(Wq, Wk, Wv, Wo, wt);
    tohalf<<<SEQ * DM / 1024, 256>>>(x, xh);

    // Fused QKV GEMM: N = 3072 (Wq^T|Wk^T|Wv^T contiguous)
    gemm_fp16<<<dim3(24, SEQ / 128), 256, GSMEM>>>(xh, wt, q, k, v);

    attn_kernel<<<dim3(SEQ / 64, NH), 128>>>();

    // Output projection
    gemm_fp16<<<dim3(8, SEQ / 128), 256, GSMEM>>>(
        ao, wt + 3 * (size_t)DM * DM, out, out, out);
}

// round 9
// speedup vs baseline: 2.3871x; 1.0768x over previous
#include <cuda_runtime.h>
#include <cuda_bf16.h>
#include <cuda_fp16.h>
#include <cstdint>

#define SEQ 4096
#define DM  1024
#define NH  16
#define DH  64
#define WIN 256

// ---------------------------------------------------------------------------
// Scratch (allocation-free rule)
// ---------------------------------------------------------------------------
__device__ __half g_qh[SEQ * DM];            // q (pre-scaled 0.125), fp16
__device__ __half g_kh[SEQ * DM];            // k, fp16
__device__ float  g_v [SEQ * DM];            // v, tf32 bit patterns
__device__ __half g_xh[SEQ * DM];            // x as fp16
__device__ __half g_ao[SEQ * DM];            // attention output as fp16
__device__ __half g_wt[4][DM * DM];          // W^T as fp16 (q,k,v,o)

// ---------------------------------------------------------------------------
// Helpers
// ---------------------------------------------------------------------------
__device__ __forceinline__ uint32_t smem_u32(const void* p) {
    uint32_t a;
    asm("{ .reg .u64 t; cvta.to.shared.u64 t, %1; cvt.u32.u64 %0, t; }" : "=r"(a) : "l"(p));
    return a;
}
__device__ __forceinline__ unsigned f2tf(float f) {
    unsigned r; asm("cvt.rna.tf32.f32 %0, %1;" : "=r"(r) : "f"(f)); return r;
}
// fp16 MMA m16n8k16
__device__ __forceinline__ void mma_fp(float* c, const unsigned* a, const unsigned* b) {
    asm volatile("mma.sync.aligned.m16n8k16.row.col.f32.f16.f16.f32 "
        "{%0,%1,%2,%3},{%4,%5,%6,%7},{%8,%9},{%0,%1,%2,%3};"
        : "+f"(c[0]), "+f"(c[1]), "+f"(c[2]), "+f"(c[3])
        : "r"(a[0]), "r"(a[1]), "r"(a[2]), "r"(a[3]), "r"(b[0]), "r"(b[1]));
}
// tf32 MMA m16n8k8
__device__ __forceinline__ void mma_tf(float* c, const unsigned* a, const unsigned* b) {
    asm volatile("mma.sync.aligned.m16n8k8.row.col.f32.tf32.tf32.f32 "
        "{%0,%1,%2,%3},{%4,%5,%6,%7},{%8,%9},{%0,%1,%2,%3};"
        : "+f"(c[0]), "+f"(c[1]), "+f"(c[2]), "+f"(c[3])
        : "r"(a[0]), "r"(a[1]), "r"(a[2]), "r"(a[3]), "r"(b[0]), "r"(b[1]));
}
#define CP16(dst, src) \
    asm volatile("cp.async.cg.shared.global [%0], [%1], 16;" :: "r"(dst), "l"(src))
#define CP_COMMIT() asm volatile("cp.async.commit_group;" ::: "memory")
#define CP_WAIT3()  asm volatile("cp.async.wait_group 3;" ::: "memory")
#define LDSM4(r0, r1, r2, r3, a) \
    asm volatile("ldmatrix.sync.aligned.m8n8.x4.shared.b16 {%0,%1,%2,%3}, [%4];" \
        : "=r"(r0), "=r"(r1), "=r"(r2), "=r"(r3) : "r"(a))

// ---------------------------------------------------------------------------
// Conversion kernels (one-time per launch)
// ---------------------------------------------------------------------------
__global__ void tohalf(const float* __restrict__ src, __half* __restrict__ dst) {
    int i = (blockIdx.x * blockDim.x + threadIdx.x) * 4;
    float4 v = *(const float4*)(src + i);
    __half2 a = __floats2half2_rn(v.x, v.y);
    __half2 b = __floats2half2_rn(v.z, v.w);
    *(uint2*)(dst + i) = make_uint2(*(unsigned*)&a, *(unsigned*)&b);
}

// All four W [K=DM][N=DM] -> W^T [N][K] fp16, one launch (grid.z = 4)
__global__ void tsplit4h(const float* __restrict__ W0, const float* __restrict__ W1,
                         const float* __restrict__ W2, const float* __restrict__ W3,
                         __half* __restrict__ T) {
    __shared__ float tile[32][33];
    const int z = blockIdx.z;
    const float* W = z == 0 ? W0 : (z == 1 ? W1 : (z == 2 ? W2 : W3));
    __half* t_out = T + (size_t)z * DM * DM;
    int k0 = blockIdx.y * 32, n0 = blockIdx.x * 32;
    int tx = threadIdx.x, ty = threadIdx.y;
#pragma unroll
    for (int j = 0; j < 32; j += 8)
        tile[ty + j][tx] = W[(size_t)(k0 + ty + j) * DM + n0 + tx];
    __syncthreads();
#pragma unroll
    for (int j = 0; j < 32; j += 8)
        t_out[(size_t)(n0 + ty + j) * DM + k0 + tx] = __float2half(tile[tx][ty + j]);
}

// ---------------------------------------------------------------------------
// Pipelined 1-pass fp16 HMMA GEMM. 256 thr (8 warps 2x4), tile 128x128, BK=16,
// 4-stage cp.async. FUSED epilogue writes q (fp16, x0.125) / k (fp16) /
// v (tf32) to the attention scratch; non-fused writes fp32 to `out`.
// ---------------------------------------------------------------------------
#define ROWB    48
#define PLANEB  (128 * ROWB)        // 6144
#define STAGEB  (2 * PLANEB)        // 12288
#define NSTAGE  4
#define GSMEM   (NSTAGE * STAGEB)   // 49152

template <bool FUSED>
__global__ void __launch_bounds__(256, 2) gemm_fp16(
    const __half* __restrict__ A, const __half* __restrict__ BT,
    float* __restrict__ out)
{
    extern __shared__ char dynsmem[];
    const uint32_t sb = smem_u32(dynsmem);
    const int tid = threadIdx.x, lane = tid & 31, warp = tid >> 5;
    const int m0 = blockIdx.y * 128;
    const int nb = blockIdx.x;
    const int nbase = nb * 128;
    const int col0 = (nb & 7) * 128;

    const int r = tid >> 1, hf = tid & 1;
    const __half* gsrcA = A  + (size_t)(m0 + r) * DM + hf * 8;
    const __half* gsrcB = BT + (size_t)(nbase + r) * DM + hf * 8;
    const uint32_t sdst = r * ROWB + hf * 16;

    const int wm = (warp >> 2) * 64, wn = (warp & 3) * 32;
    const int lrow = lane & 15, lcol = lane & 16;
    const uint32_t abase = (wm + lrow) * ROWB + lcol;
    const uint32_t bbase = (wn + lrow) * ROWB + lcol;

    float acc[4][4][4];
#pragma unroll
    for (int a = 0; a < 4; a++)
#pragma unroll
        for (int b = 0; b < 4; b++)
#pragma unroll
            for (int c = 0; c < 4; c++) acc[a][b][c] = 0.0f;

#pragma unroll
    for (int t = 0; t < NSTAGE; t++) {
        const uint32_t st = sb + t * STAGEB;
        const int kc = t * 16;
        CP16(st + sdst,          gsrcA + kc);
        CP16(st + PLANEB + sdst, gsrcB + kc);
        CP_COMMIT();
    }

    const int KT = DM / 16;  // 64
    for (int t = 0; t < KT; t++) {
        CP_WAIT3();
        __syncthreads();
        const uint32_t st = sb + (t % NSTAGE) * STAGEB;

        unsigned bf[4][2];
#pragma unroll
        for (int j = 0; j < 2; j++) {
            unsigned r0, r1, r2, r3;
            LDSM4(r0, r1, r2, r3, st + PLANEB + bbase + j * (16 * ROWB));
            bf[2 * j][0] = r0; bf[2 * j + 1][0] = r1;
            bf[2 * j][1] = r2; bf[2 * j + 1][1] = r3;
        }
#pragma unroll
        for (int mt = 0; mt < 4; mt++) {
            unsigned af[4];
            LDSM4(af[0], af[1], af[2], af[3], st + abase + mt * (16 * ROWB));
#pragma unroll
            for (int nt = 0; nt < 4; nt++)
                mma_fp(acc[mt][nt], af, bf[nt]);
        }
        __syncthreads();

        if (t + NSTAGE < KT) {
            const int kc = (t + NSTAGE) * 16;
            CP16(st + sdst,          gsrcA + kc);
            CP16(st + PLANEB + sdst, gsrcB + kc);
        }
        CP_COMMIT();
    }

    const int g = lane >> 2, tig = lane & 3;
    if (!FUSED) {
#pragma unroll
        for (int mt = 0; mt < 4; mt++)
#pragma unroll
            for (int nt = 0; nt < 4; nt++) {
                int row = m0 + wm + mt * 16 + g;
                int cc = col0 + wn + nt * 8 + 2 * tig;
                *(float2*)(out + (size_t)row * DM + cc) =
                    make_float2(acc[mt][nt][0], acc[mt][nt][1]);
                *(float2*)(out + (size_t)(row + 8) * DM + cc) =
                    make_float2(acc[mt][nt][2], acc[mt][nt][3]);
            }
    } else {
        const int grp = nb >> 3;   // 0=q, 1=k, 2=v (uniform per block)
#pragma unroll
        for (int mt = 0; mt < 4; mt++)
#pragma unroll
            for (int nt = 0; nt < 4; nt++) {
                int row = m0 + wm + mt * 16 + g;
                int cc = col0 + wn + nt * 8 + 2 * tig;
                if (grp == 0) {
                    __half2 h0 = __floats2half2_rn(acc[mt][nt][0] * 0.125f,
                                                   acc[mt][nt][1] * 0.125f);
                    __half2 h1 = __floats2half2_rn(acc[mt][nt][2] * 0.125f,
                                                   acc[mt][nt][3] * 0.125f);
                    *(unsigned*)(g_qh + (size_t)row * DM + cc) = *(unsigned*)&h0;
                    *(unsigned*)(g_qh + (size_t)(row + 8) * DM + cc) = *(unsigned*)&h1;
                } else if (grp == 1) {
                    __half2 h0 = __floats2half2_rn(acc[mt][nt][0], acc[mt][nt][1]);
                    __half2 h1 = __floats2half2_rn(acc[mt][nt][2], acc[mt][nt][3]);
                    *(unsigned*)(g_kh + (size_t)row * DM + cc) = *(unsigned*)&h0;
                    *(unsigned*)(g_kh + (size_t)(row + 8) * DM + cc) = *(unsigned*)&h1;
                } else {
                    *(float2*)(g_v + (size_t)row * DM + cc) = make_float2(
                        __uint_as_float(f2tf(acc[mt][nt][0])),
                        __uint_as_float(f2tf(acc[mt][nt][1])));
                    *(float2*)(g_v + (size_t)(row + 8) * DM + cc) = make_float2(
                        __uint_as_float(f2tf(acc[mt][nt][2])),
                        __uint_as_float(f2tf(acc[mt][nt][3])));
                }
            }
    }
}

// ---------------------------------------------------------------------------
// Warp-tiled flash attention. QK^T: 1-pass fp16 (q pre-scaled), PV: tf32.
// Staging is pure copies (q/k fp16, v tf32 pre-converted by the GEMM).
// Grid (SEQ/64, NH), 128 threads (4 warps, 16 query rows each).
// Descending chunk order keeps the first computed chunk on the diagonal.
// ---------------------------------------------------------------------------
__global__ void __launch_bounds__(128) attn_kernel()
{
    __shared__ unsigned Qh[64][36];   // fp16 pairs; reused as P-stage (tf32)
    __shared__ unsigned Kh[32][36];   // fp16 pairs
    __shared__ unsigned Vs[32][72];   // tf32

    const int h = blockIdx.y, t0 = blockIdx.x * 64;
    const int tid = threadIdx.x;
    const int lane = tid & 31, warp = tid >> 5;
    const int g = lane >> 2, tig = lane & 3;
    const int wq = t0 + warp * 16;

    // Stage Q: 64 rows x 64 fp16 = 512 x 16B
#pragma unroll
    for (int u = 0; u < 4; u++) {
        int idx = tid + u * 128;
        int r = idx >> 3, c = idx & 7;
        *(uint4*)&Qh[r][c * 4] =
            *(const uint4*)(g_qh + (size_t)(t0 + r) * DM + h * DH + c * 8);
    }
    __syncthreads();

    // Q fragments: A(m16 x k16) per kstep, 4 ksteps cover DH=64
    unsigned qf[4][4];
    const int rA = warp * 16 + g;
#pragma unroll
    for (int ks = 0; ks < 4; ks++) {
        qf[ks][0] = Qh[rA][ks * 8 + tig];     qf[ks][1] = Qh[rA + 8][ks * 8 + tig];
        qf[ks][2] = Qh[rA][ks * 8 + tig + 4]; qf[ks][3] = Qh[rA + 8][ks * 8 + tig + 4];
    }
    __syncwarp();  // q-frag reads done before Qh is reused as P-stage

    float o[8][4];
#pragma unroll
    for (int nt = 0; nt < 8; nt++)
#pragma unroll
        for (int e = 0; e < 4; e++) o[nt][e] = 0.0f;
    float m0 = -1e30f, m1 = -1e30f, l0 = 0.0f, l1 = 0.0f;

    const int jlo = max(0, t0 - WIN);
    const int jtop_w = ((wq + 15) >> 5) << 5;

    for (int jc = t0 + 32; jc >= jlo; jc -= 32) {
        __syncthreads();
        // Stage K (fp16): 32 rows x 8 x 16B = 256; V (tf32): 32 x 16 x 16B = 512
#pragma unroll
        for (int u = 0; u < 2; u++) {
            int idx = tid + u * 128;
            int r = idx >> 3, c = idx & 7;
            *(uint4*)&Kh[r][c * 4] =
                *(const uint4*)(g_kh + (size_t)(jc + r) * DM + h * DH + c * 8);
        }
#pragma unroll
        for (int u = 0; u < 4; u++) {
            int idx = tid + u * 128;
            int r = idx >> 4, c = idx & 15;
            *(uint4*)&Vs[r][c * 4] =
                *(const uint4*)((const unsigned*)g_v + (size_t)(jc + r) * DM + h * DH + c * 4);
        }
        __syncthreads();

        if (jc <= jtop_w && jc + 31 + WIN >= wq) {
            // Scores: S(16x32) = Q @ K^T, 1-pass fp16 (16 MMAs)
            float s[4][4];
#pragma unroll
            for (int nt = 0; nt < 4; nt++)
#pragma unroll
                for (int e = 0; e < 4; e++) s[nt][e] = 0.0f;
#pragma unroll
            for (int ks = 0; ks < 4; ks++) {
#pragma unroll
                for (int nt = 0; nt < 4; nt++) {
                    unsigned bf[2];
                    bf[0] = Kh[nt * 8 + g][ks * 8 + tig];
                    bf[1] = Kh[nt * 8 + g][ks * 8 + tig + 4];
                    mma_fp(s[nt], qf[ks], bf);
                }
            }

            // Mask + online softmax (rows r0 = wq+g, r1 = r0+8)
            const int r0 = wq + g, r1 = r0 + 8;
            float mx0 = -1e30f, mx1 = -1e30f;
#pragma unroll
            for (int nt = 0; nt < 4; nt++) {
#pragma unroll
                for (int e = 0; e < 2; e++) {
                    int j = jc + nt * 8 + 2 * tig + e;
                    if (j > r0 || j + WIN < r0) s[nt][e] = -1e30f;
                    if (j > r1 || j + WIN < r1) s[nt][2 + e] = -1e30f;
                    mx0 = fmaxf(mx0, s[nt][e]);
                    mx1 = fmaxf(mx1, s[nt][2 + e]);
                }
            }
            mx0 = fmaxf(mx0, __shfl_xor_sync(0xffffffffu, mx0, 1));
            mx0 = fmaxf(mx0, __shfl_xor_sync(0xffffffffu, mx0, 2));
            mx1 = fmaxf(mx1, __shfl_xor_sync(0xffffffffu, mx1, 1));
            mx1 = fmaxf(mx1, __shfl_xor_sync(0xffffffffu, mx1, 2));
            float mn0 = fmaxf(m0, mx0), mn1 = fmaxf(m1, mx1);
            float c0 = __expf(m0 - mn0), c1 = __expf(m1 - mn1);
            m0 = mn0; m1 = mn1;
            l0 *= c0; l1 *= c1;
#pragma unroll
            for (int nt = 0; nt < 8; nt++) {
                o[nt][0] *= c0; o[nt][1] *= c0;
                o[nt][2] *= c1; o[nt][3] *= c1;
            }
            float ls0 = 0.0f, ls1 = 0.0f;
#pragma unroll
            for (int nt = 0; nt < 4; nt++) {
                float p00 = __expf(s[nt][0] - mn0), p01 = __expf(s[nt][1] - mn0);
                float p10 = __expf(s[nt][2] - mn1), p11 = __expf(s[nt][3] - mn1);
                ls0 += p00 + p01; ls1 += p10 + p11;
                uint2 w0; w0.x = f2tf(p00); w0.y = f2tf(p01);
                uint2 w1; w1.x = f2tf(p10); w1.y = f2tf(p11);
                *(uint2*)&Qh[rA][nt * 8 + 2 * tig] = w0;           // P-stage (tf32)
                *(uint2*)&Qh[rA + 8][nt * 8 + 2 * tig] = w1;
            }
            ls0 += __shfl_xor_sync(0xffffffffu, ls0, 1);
            ls0 += __shfl_xor_sync(0xffffffffu, ls0, 2);
            ls1 += __shfl_xor_sync(0xffffffffu, ls1, 1);
            ls1 += __shfl_xor_sync(0xffffffffu, ls1, 2);
            l0 += ls0; l1 += ls1;
            __syncwarp();

            // O += P(16x32) @ V(32x64), tf32
#pragma unroll
            for (int ks2 = 0; ks2 < 4; ks2++) {
                unsigned pa[4];
                pa[0] = Qh[rA][ks2 * 8 + tig];
                pa[1] = Qh[rA + 8][ks2 * 8 + tig];
                pa[2] = Qh[rA][ks2 * 8 + tig + 4];
                pa[3] = Qh[rA + 8][ks2 * 8 + tig + 4];
#pragma unroll
                for (int nt = 0; nt < 8; nt++) {
                    unsigned vb[2];
                    vb[0] = Vs[ks2 * 8 + tig][nt * 8 + g];
                    vb[1] = Vs[ks2 * 8 + tig + 4][nt * 8 + g];
                    mma_tf(o[nt], pa, vb);
                }
            }
        }
    }

    // Epilogue: normalize + fp16 for the O-projection GEMM
    const float inv0 = 1.0f / l0, inv1 = 1.0f / l1;
#pragma unroll
    for (int nt = 0; nt < 8; nt++) {
        int col = h * DH + nt * 8 + 2 * tig;
        __half2 a = __floats2half2_rn(o[nt][0] * inv0, o[nt][1] * inv0);
        __half2 b = __floats2half2_rn(o[nt][2] * inv1, o[nt][3] * inv1);
        *(unsigned*)(g_ao + (size_t)(wq + g) * DM + col) = *(unsigned*)&a;
        *(unsigned*)(g_ao + (size_t)(wq + g + 8) * DM + col) = *(unsigned*)&b;
    }
}

// ---------------------------------------------------------------------------
extern "C" void kernel_launch(void* const* d_in, const int* in_sizes, int n_in,
                              void* d_out, int out_size)
{
    const float* x  = (const float*)d_in[0];
    const float* Wq = (const float*)d_in[1];
    const float* Wk = (const float*)d_in[2];
    const float* Wv = (const float*)d_in[3];
    const float* Wo = (const float*)d_in[4];
    float* out = (float*)d_out;

    __half *xh, *ao, *wt;
    cudaGetSymbolAddress((void**)&xh, g_xh);
    cudaGetSymbolAddress((void**)&ao, g_ao);
    cudaGetSymbolAddress((void**)&wt, g_wt);

    cudaFuncSetAttribute(gemm_fp16<true>,  cudaFuncAttributeMaxDynamicSharedMemorySize, GSMEM);
    cudaFuncSetAttribute(gemm_fp16<false>, cudaFuncAttributeMaxDynamicSharedMemorySize, GSMEM);

    // One-time conversions
    tsplit4h<<<dim3(DM / 32, DM / 32, 4), dim3(32, 8)>>>(Wq, Wk, Wv, Wo, wt);
    tohalf<<<SEQ * DM / 1024, 256>>>(x, xh);

    // Fused QKV GEMM: N = 3072; epilogue writes q(fp16,x0.125)/k(fp16)/v(tf32)
    gemm_fp16<true><<<dim3(24, SEQ / 128), 256, GSMEM>>>(xh, wt, nullptr);

    attn_kernel<<<dim3(SEQ / 64, NH), 128>>>();

    // Output projection (fp32 out)
    gemm_fp16<false><<<dim3(8, SEQ / 128), 256, GSMEM>>>(
        ao, wt + 3 * (size_t)DM * DM, out);
}

// round 10
// speedup vs baseline: 2.5308x; 1.0602x over previous
#include <cuda_runtime.h>
#include <cuda_bf16.h>
#include <cuda_fp16.h>
#include <cstdint>

#define SEQ 4096
#define DM  1024
#define NH  16
#define DH  64
#define WIN 256

// ---------------------------------------------------------------------------
// Scratch (allocation-free rule)
// ---------------------------------------------------------------------------
__device__ __half    g_qh[SEQ * DM];          // q (pre-scaled 0.125*log2e), fp16
__device__ __half    g_kh[SEQ * DM];          // k, fp16
__device__ unsigned  g_vp[(SEQ / 2) * DM];    // v, fp16 k-pair-packed: [p][c]=(v[2p][c],v[2p+1][c])
__device__ __half    g_xh[SEQ * DM];          // x as fp16
__device__ __half    g_ao[SEQ * DM];          // attention output as fp16
__device__ __half    g_wt[4][DM * DM];        // W^T as fp16 (q,k,v,o)

// ---------------------------------------------------------------------------
// Helpers
// ---------------------------------------------------------------------------
__device__ __forceinline__ uint32_t smem_u32(const void* p) {
    uint32_t a;
    asm("{ .reg .u64 t; cvta.to.shared.u64 t, %1; cvt.u32.u64 %0, t; }" : "=r"(a) : "l"(p));
    return a;
}
__device__ __forceinline__ float ex2(float x) {
    float r; asm("ex2.approx.ftz.f32 %0, %1;" : "=f"(r) : "f"(x)); return r;
}
// fp16 MMA m16n8k16, fp32 accum
__device__ __forceinline__ void mma_fp(float* c, const unsigned* a, const unsigned* b) {
    asm volatile("mma.sync.aligned.m16n8k16.row.col.f32.f16.f16.f32 "
        "{%0,%1,%2,%3},{%4,%5,%6,%7},{%8,%9},{%0,%1,%2,%3};"
        : "+f"(c[0]), "+f"(c[1]), "+f"(c[2]), "+f"(c[3])
        : "r"(a[0]), "r"(a[1]), "r"(a[2]), "r"(a[3]), "r"(b[0]), "r"(b[1]));
}
#define CP16(dst, src) \
    asm volatile("cp.async.cg.shared.global [%0], [%1], 16;" :: "r"(dst), "l"(src))
#define CP_COMMIT() asm volatile("cp.async.commit_group;" ::: "memory")
#define CP_WAIT3()  asm volatile("cp.async.wait_group 3;" ::: "memory")
#define LDSM4(r0, r1, r2, r3, a) \
    asm volatile("ldmatrix.sync.aligned.m8n8.x4.shared.b16 {%0,%1,%2,%3}, [%4];" \
        : "=r"(r0), "=r"(r1), "=r"(r2), "=r"(r3) : "r"(a))

// q scale: 0.125 (1/sqrt(64)) * log2(e), folded so softmax can use exp2
#define QSCALE 0.180336880f

// ---------------------------------------------------------------------------
// Conversion kernels (one-time per launch)
// ---------------------------------------------------------------------------
__global__ void tohalf(const float* __restrict__ src, __half* __restrict__ dst) {
    int i = (blockIdx.x * blockDim.x + threadIdx.x) * 4;
    float4 v = *(const float4*)(src + i);
    __half2 a = __floats2half2_rn(v.x, v.y);
    __half2 b = __floats2half2_rn(v.z, v.w);
    *(uint2*)(dst + i) = make_uint2(*(unsigned*)&a, *(unsigned*)&b);
}

// All four W [K=DM][N=DM] -> W^T [N][K] fp16, one launch (grid.z = 4)
__global__ void tsplit4h(const float* __restrict__ W0, const float* __restrict__ W1,
                         const float* __restrict__ W2, const float* __restrict__ W3,
                         __half* __restrict__ T) {
    __shared__ float tile[32][33];
    const int z = blockIdx.z;
    const float* W = z == 0 ? W0 : (z == 1 ? W1 : (z == 2 ? W2 : W3));
    __half* t_out = T + (size_t)z * DM * DM;
    int k0 = blockIdx.y * 32, n0 = blockIdx.x * 32;
    int tx = threadIdx.x, ty = threadIdx.y;
#pragma unroll
    for (int j = 0; j < 32; j += 8)
        tile[ty + j][tx] = W[(size_t)(k0 + ty + j) * DM + n0 + tx];
    __syncthreads();
#pragma unroll
    for (int j = 0; j < 32; j += 8)
        t_out[(size_t)(n0 + ty + j) * DM + k0 + tx] = __float2half(tile[tx][ty + j]);
}

// ---------------------------------------------------------------------------
// Pipelined 1-pass fp16 HMMA GEMM. 256 thr (8 warps 2x4), tile 128x128, BK=16,
// 4-stage cp.async. FUSED epilogue writes q (fp16, xQSCALE) / k (fp16) /
// v (fp16, k-pair-packed via shfl) to attention scratch; else fp32 to `out`.
// ---------------------------------------------------------------------------
#define ROWB    48
#define PLANEB  (128 * ROWB)        // 6144
#define STAGEB  (2 * PLANEB)        // 12288
#define NSTAGE  4
#define GSMEM   (NSTAGE * STAGEB)   // 49152

template <bool FUSED>
__global__ void __launch_bounds__(256, 2) gemm_fp16(
    const __half* __restrict__ A, const __half* __restrict__ BT,
    float* __restrict__ out)
{
    extern __shared__ char dynsmem[];
    const uint32_t sb = smem_u32(dynsmem);
    const int tid = threadIdx.x, lane = tid & 31, warp = tid >> 5;
    const int m0 = blockIdx.y * 128;
    const int nb = blockIdx.x;
    const int nbase = nb * 128;
    const int col0 = (nb & 7) * 128;

    const int r = tid >> 1, hf = tid & 1;
    const __half* gsrcA = A  + (size_t)(m0 + r) * DM + hf * 8;
    const __half* gsrcB = BT + (size_t)(nbase + r) * DM + hf * 8;
    const uint32_t sdst = r * ROWB + hf * 16;

    const int wm = (warp >> 2) * 64, wn = (warp & 3) * 32;
    const int lrow = lane & 15, lcol = lane & 16;
    const uint32_t abase = (wm + lrow) * ROWB + lcol;
    const uint32_t bbase = (wn + lrow) * ROWB + lcol;

    float acc[4][4][4];
#pragma unroll
    for (int a = 0; a < 4; a++)
#pragma unroll
        for (int b = 0; b < 4; b++)
#pragma unroll
            for (int c = 0; c < 4; c++) acc[a][b][c] = 0.0f;

#pragma unroll
    for (int t = 0; t < NSTAGE; t++) {
        const uint32_t st = sb + t * STAGEB;
        const int kc = t * 16;
        CP16(st + sdst,          gsrcA + kc);
        CP16(st + PLANEB + sdst, gsrcB + kc);
        CP_COMMIT();
    }

    const int KT = DM / 16;  // 64
    for (int t = 0; t < KT; t++) {
        CP_WAIT3();
        __syncthreads();
        const uint32_t st = sb + (t % NSTAGE) * STAGEB;

        unsigned bf[4][2];
#pragma unroll
        for (int j = 0; j < 2; j++) {
            unsigned r0, r1, r2, r3;
            LDSM4(r0, r1, r2, r3, st + PLANEB + bbase + j * (16 * ROWB));
            bf[2 * j][0] = r0; bf[2 * j + 1][0] = r1;
            bf[2 * j][1] = r2; bf[2 * j + 1][1] = r3;
        }
#pragma unroll
        for (int mt = 0; mt < 4; mt++) {
            unsigned af[4];
            LDSM4(af[0], af[1], af[2], af[3], st + abase + mt * (16 * ROWB));
#pragma unroll
            for (int nt = 0; nt < 4; nt++)
                mma_fp(acc[mt][nt], af, bf[nt]);
        }
        __syncthreads();

        if (t + NSTAGE < KT) {
            const int kc = (t + NSTAGE) * 16;
            CP16(st + sdst,          gsrcA + kc);
            CP16(st + PLANEB + sdst, gsrcB + kc);
        }
        CP_COMMIT();
    }

    const int g = lane >> 2, tig = lane & 3;
    if (!FUSED) {
#pragma unroll
        for (int mt = 0; mt < 4; mt++)
#pragma unroll
            for (int nt = 0; nt < 4; nt++) {
                int row = m0 + wm + mt * 16 + g;
                int cc = col0 + wn + nt * 8 + 2 * tig;
                *(float2*)(out + (size_t)row * DM + cc) =
                    make_float2(acc[mt][nt][0], acc[mt][nt][1]);
                *(float2*)(out + (size_t)(row + 8) * DM + cc) =
                    make_float2(acc[mt][nt][2], acc[mt][nt][3]);
            }
    } else {
        const int grp = nb >> 3;   // 0=q, 1=k, 2=v (uniform per block)
#pragma unroll
        for (int mt = 0; mt < 4; mt++)
#pragma unroll
            for (int nt = 0; nt < 4; nt++) {
                int row = m0 + wm + mt * 16 + g;
                int cc = col0 + wn + nt * 8 + 2 * tig;
                if (grp == 0) {
                    __half2 h0 = __floats2half2_rn(acc[mt][nt][0] * QSCALE,
                                                   acc[mt][nt][1] * QSCALE);
                    __half2 h1 = __floats2half2_rn(acc[mt][nt][2] * QSCALE,
                                                   acc[mt][nt][3] * QSCALE);
                    *(unsigned*)(g_qh + (size_t)row * DM + cc) = *(unsigned*)&h0;
                    *(unsigned*)(g_qh + (size_t)(row + 8) * DM + cc) = *(unsigned*)&h1;
                } else if (grp == 1) {
                    __half2 h0 = __floats2half2_rn(acc[mt][nt][0], acc[mt][nt][1]);
                    __half2 h1 = __floats2half2_rn(acc[mt][nt][2], acc[mt][nt][3]);
                    *(unsigned*)(g_kh + (size_t)row * DM + cc) = *(unsigned*)&h0;
                    *(unsigned*)(g_kh + (size_t)(row + 8) * DM + cc) = *(unsigned*)&h1;
                } else {
                    // V: k-pair-packed fp16. Lane (g even) pairs its rows (r, r+8)
                    // with lane+4's rows (r+1, r+9).
                    float a0 = acc[mt][nt][0], a1 = acc[mt][nt][1];
                    float a2 = acc[mt][nt][2], a3 = acc[mt][nt][3];
                    float b0 = __shfl_down_sync(0xffffffffu, a0, 4);
                    float b1 = __shfl_down_sync(0xffffffffu, a1, 4);
                    float b2 = __shfl_down_sync(0xffffffffu, a2, 4);
                    float b3 = __shfl_down_sync(0xffffffffu, a3, 4);
                    if (!(g & 1)) {
                        int prow = row >> 1;                 // pair (row, row+1)
                        __half2 p0 = __floats2half2_rn(a0, b0);   // col cc
                        __half2 p1 = __floats2half2_rn(a1, b1);   // col cc+1
                        *(uint2*)(g_vp + (size_t)prow * DM + cc) =
                            make_uint2(*(unsigned*)&p0, *(unsigned*)&p1);
                        __half2 p2 = __floats2half2_rn(a2, b2);   // pair (row+8, row+9)
                        __half2 p3 = __floats2half2_rn(a3, b3);
                        *(uint2*)(g_vp + (size_t)(prow + 4) * DM + cc) =
                            make_uint2(*(unsigned*)&p2, *(unsigned*)&p3);
                    }
                }
            }
    }
}

// ---------------------------------------------------------------------------
// Warp-tiled flash attention. Chunk = 64 keys. QK^T and P@V both 1-pass fp16
// m16n8k16 (V and P k-pair-packed). Softmax in exp2 domain (scale folded into
// q by the GEMM). Grid (SEQ/64, NH), 128 threads (4 warps x 16 query rows).
// Descending chunks: first computed chunk (jc=t0) contains every diagonal.
// ---------------------------------------------------------------------------
__global__ void __launch_bounds__(128, 4) attn_kernel()
{
    __shared__ unsigned Qh[64][36];   // q fp16 pairs (head-dim-packed)
    __shared__ unsigned Kh[64][36];   // k fp16 pairs
    __shared__ unsigned Vs[32][72];   // v fp16 k-pair-packed: 32 pair-rows x 64 cols
    __shared__ unsigned Ps[64][36];   // P fp16 k-pair-packed: 64 rows x 32 pair-cols

    const int h = blockIdx.y, t0 = blockIdx.x * 64;
    const int tid = threadIdx.x;
    const int lane = tid & 31, warp = tid >> 5;
    const int g = lane >> 2, tig = lane & 3;
    const int wq = t0 + warp * 16;
    const int rA = warp * 16 + g;

    // Stage Q: 64 rows x 8 uint4
#pragma unroll
    for (int u = 0; u < 4; u++) {
        int idx = tid + u * 128;
        int r = idx >> 3, c = idx & 7;
        *(uint4*)&Qh[r][c * 4] =
            *(const uint4*)(g_qh + (size_t)(t0 + r) * DM + h * DH + c * 8);
    }

    float o[8][4];
#pragma unroll
    for (int nt = 0; nt < 8; nt++)
#pragma unroll
        for (int e = 0; e < 4; e++) o[nt][e] = 0.0f;
    float m0 = -1e30f, m1 = -1e30f, l0 = 0.0f, l1 = 0.0f;

    const int jlo = max(0, t0 - WIN);

    for (int jc = t0; jc >= jlo; jc -= 64) {
        __syncthreads();   // prev chunk's Kh/Vs reads done (also orders Q staging)
        // Stage K: 64 rows x 8 uint4; V: 32 pair-rows x 16 uint4
#pragma unroll
        for (int u = 0; u < 4; u++) {
            int idx = tid + u * 128;
            int r = idx >> 3, c = idx & 7;
            *(uint4*)&Kh[r][c * 4] =
                *(const uint4*)(g_kh + (size_t)(jc + r) * DM + h * DH + c * 8);
        }
#pragma unroll
        for (int u = 0; u < 4; u++) {
            int idx = tid + u * 128;
            int r = idx >> 4, c = idx & 15;
            *(uint4*)&Vs[r][c * 4] =
                *(const uint4*)(g_vp + (size_t)((jc >> 1) + r) * DM + h * DH + c * 4);
        }
        __syncthreads();

        // Scores: S(16x64) = Q @ K^T (32 fp16 MMAs)
        float s[8][4];
#pragma unroll
        for (int nt = 0; nt < 8; nt++)
#pragma unroll
            for (int e = 0; e < 4; e++) s[nt][e] = 0.0f;
#pragma unroll
        for (int ks = 0; ks < 4; ks++) {
            unsigned qf[4];
            qf[0] = Qh[rA][ks * 8 + tig];     qf[1] = Qh[rA + 8][ks * 8 + tig];
            qf[2] = Qh[rA][ks * 8 + tig + 4]; qf[3] = Qh[rA + 8][ks * 8 + tig + 4];
#pragma unroll
            for (int nt = 0; nt < 8; nt++) {
                unsigned bf[2];
                bf[0] = Kh[nt * 8 + g][ks * 8 + tig];
                bf[1] = Kh[nt * 8 + g][ks * 8 + tig + 4];
                mma_fp(s[nt], qf, bf);
            }
        }

        // Mask + online softmax (rows r0 = wq+g, r1 = r0+8), exp2 domain
        const int r0 = wq + g, r1 = r0 + 8;
        float mx0 = -1e30f, mx1 = -1e30f;
#pragma unroll
        for (int nt = 0; nt < 8; nt++) {
#pragma unroll
            for (int e = 0; e < 2; e++) {
                int j = jc + nt * 8 + 2 * tig + e;
                if (j > r0 || j + WIN < r0) s[nt][e] = -1e30f;
                if (j > r1 || j + WIN < r1) s[nt][2 + e] = -1e30f;
                mx0 = fmaxf(mx0, s[nt][e]);
                mx1 = fmaxf(mx1, s[nt][2 + e]);
            }
        }
        mx0 = fmaxf(mx0, __shfl_xor_sync(0xffffffffu, mx0, 1));
        mx0 = fmaxf(mx0, __shfl_xor_sync(0xffffffffu, mx0, 2));
        mx1 = fmaxf(mx1, __shfl_xor_sync(0xffffffffu, mx1, 1));
        mx1 = fmaxf(mx1, __shfl_xor_sync(0xffffffffu, mx1, 2));
        float mn0 = fmaxf(m0, mx0), mn1 = fmaxf(m1, mx1);
        float c0 = ex2(m0 - mn0), c1 = ex2(m1 - mn1);
        m0 = mn0; m1 = mn1;
        l0 *= c0; l1 *= c1;
#pragma unroll
        for (int nt = 0; nt < 8; nt++) {
            o[nt][0] *= c0; o[nt][1] *= c0;
            o[nt][2] *= c1; o[nt][3] *= c1;
        }
        float ls0 = 0.0f, ls1 = 0.0f;
#pragma unroll
        for (int nt = 0; nt < 8; nt++) {
            float p00 = ex2(s[nt][0] - mn0), p01 = ex2(s[nt][1] - mn0);
            float p10 = ex2(s[nt][2] - mn1), p11 = ex2(s[nt][3] - mn1);
            ls0 += p00 + p01; ls1 += p10 + p11;
            __half2 w0 = __floats2half2_rn(p00, p01);
            __half2 w1 = __floats2half2_rn(p10, p11);
            Ps[rA][nt * 4 + tig] = *(unsigned*)&w0;
            Ps[rA + 8][nt * 4 + tig] = *(unsigned*)&w1;
        }
        ls0 += __shfl_xor_sync(0xffffffffu, ls0, 1);
        ls0 += __shfl_xor_sync(0xffffffffu, ls0, 2);
        ls1 += __shfl_xor_sync(0xffffffffu, ls1, 1);
        ls1 += __shfl_xor_sync(0xffffffffu, ls1, 2);
        l0 += ls0; l1 += ls1;
        __syncwarp();   // Ps rows are warp-private; warp-level ordering suffices

        // O += P(16x64) @ V(64x64), fp16 (32 MMAs)
#pragma unroll
        for (int ks2 = 0; ks2 < 4; ks2++) {
            unsigned pa[4];
            pa[0] = Ps[rA][ks2 * 8 + tig];
            pa[1] = Ps[rA + 8][ks2 * 8 + tig];
            pa[2] = Ps[rA][ks2 * 8 + tig + 4];
            pa[3] = Ps[rA + 8][ks2 * 8 + tig + 4];
#pragma unroll
            for (int nt = 0; nt < 8; nt++) {
                unsigned vb[2];
                vb[0] = Vs[ks2 * 8 + tig][nt * 8 + g];
                vb[1] = Vs[ks2 * 8 + tig + 4][nt * 8 + g];
                mma_fp(o[nt], pa, vb);
            }
        }
    }

    // Epilogue: normalize + fp16 for the O-projection GEMM
    const float inv0 = 1.0f / l0, inv1 = 1.0f / l1;
#pragma unroll
    for (int nt = 0; nt < 8; nt++) {
        int col = h * DH + nt * 8 + 2 * tig;
        __half2 a = __floats2half2_rn(o[nt][0] * inv0, o[nt][1] * inv0);
        __half2 b = __floats2half2_rn(o[nt][2] * inv1, o[nt][3] * inv1);
        *(unsigned*)(g_ao + (size_t)(wq + g) * DM + col) = *(unsigned*)&a;
        *(unsigned*)(g_ao + (size_t)(wq + g + 8) * DM + col) = *(unsigned*)&b;
    }
}

// ---------------------------------------------------------------------------
extern "C" void kernel_launch(void* const* d_in, const int* in_sizes, int n_in,
                              void* d_out, int out_size)
{
    const float* x  = (const float*)d_in[0];
    const float* Wq = (const float*)d_in[1];
    const float* Wk = (const float*)d_in[2];
    const float* Wv = (const float*)d_in[3];
    const float* Wo = (const float*)d_in[4];
    float* out = (float*)d_out;

    __half *xh, *ao, *wt;
    cudaGetSymbolAddress((void**)&xh, g_xh);
    cudaGetSymbolAddress((void**)&ao, g_ao);
    cudaGetSymbolAddress((void**)&wt, g_wt);

    cudaFuncSetAttribute(gemm_fp16<true>,  cudaFuncAttributeMaxDynamicSharedMemorySize, GSMEM);
    cudaFuncSetAttribute(gemm_fp16<false>, cudaFuncAttributeMaxDynamicSharedMemorySize, GSMEM);

    // One-time conversions
    tsplit4h<<<dim3(DM / 32, DM / 32, 4), dim3(32, 8)>>>(Wq, Wk, Wv, Wo, wt);
    tohalf<<<SEQ * DM / 1024, 256>>>(x, xh);

    // Fused QKV GEMM: N = 3072; epilogue writes q(fp16,xQSCALE)/k(fp16)/v(paired fp16)
    gemm_fp16<true><<<dim3(24, SEQ / 128), 256, GSMEM>>>(xh, wt, nullptr);

    attn_kernel<<<dim3(SEQ / 64, NH), 128>>>();

    // Output projection (fp32 out)
    gemm_fp16<false><<<dim3(8, SEQ / 128), 256, GSMEM>>>(
        ao, wt + 3 * (size_t)DM * DM, out);
}

// round 12
// speedup vs baseline: 2.9008x; 1.1462x over previous
#include <cuda_runtime.h>
#include <cuda_bf16.h>
#include <cuda_fp16.h>
#include <cstdint>

#define SEQ 4096
#define DM  1024
#define NH  16
#define DH  64
#define WIN 256

// ---------------------------------------------------------------------------
// Scratch (allocation-free rule)
// ---------------------------------------------------------------------------
__device__ __half    g_qh[SEQ * DM];          // q (pre-scaled 0.125*log2e), fp16
__device__ __half    g_kh[SEQ * DM];          // k, fp16
__device__ unsigned  g_vp[(SEQ / 2) * DM];    // v, fp16 k-pair-packed
__device__ __half    g_xh[SEQ * DM];          // x as fp16
__device__ __half    g_ao[SEQ * DM];          // attention output as fp16
__device__ __half    g_wt[4][DM * DM];        // W^T as fp16 (q,k,v,o)

// ---------------------------------------------------------------------------
// Helpers
// ---------------------------------------------------------------------------
__device__ __forceinline__ uint32_t smem_u32(const void* p) {
    uint32_t a;
    asm("{ .reg .u64 t; cvta.to.shared.u64 t, %1; cvt.u32.u64 %0, t; }" : "=r"(a) : "l"(p));
    return a;
}
__device__ __forceinline__ float ex2(float x) {
    float r; asm("ex2.approx.ftz.f32 %0, %1;" : "=f"(r) : "f"(x)); return r;
}
// fp16 MMA m16n8k16, fp32 accum
__device__ __forceinline__ void mma_fp(float* c, const unsigned* a, const unsigned* b) {
    asm volatile("mma.sync.aligned.m16n8k16.row.col.f32.f16.f16.f32 "
        "{%0,%1,%2,%3},{%4,%5,%6,%7},{%8,%9},{%0,%1,%2,%3};"
        : "+f"(c[0]), "+f"(c[1]), "+f"(c[2]), "+f"(c[3])
        : "r"(a[0]), "r"(a[1]), "r"(a[2]), "r"(a[3]), "r"(b[0]), "r"(b[1]));
}
#define CP16(dst, src) \
    asm volatile("cp.async.cg.shared.global [%0], [%1], 16;" :: "r"(dst), "l"(src))
#define CP_COMMIT() asm volatile("cp.async.commit_group;" ::: "memory")
#define CP_WAIT2()  asm volatile("cp.async.wait_group 2;" ::: "memory")
#define LDSM4(r0, r1, r2, r3, a) \
    asm volatile("ldmatrix.sync.aligned.m8n8.x4.shared.b16 {%0,%1,%2,%3}, [%4];" \
        : "=r"(r0), "=r"(r1), "=r"(r2), "=r"(r3) : "r"(a))

// q scale: 0.125 (1/sqrt(64)) * log2(e), folded so softmax can use exp2
#define QSCALE 0.180336880f

// ---------------------------------------------------------------------------
// Conversion kernels (one-time per launch)
// ---------------------------------------------------------------------------
__global__ void tohalf(const float* __restrict__ src, __half* __restrict__ dst) {
    int i = (blockIdx.x * blockDim.x + threadIdx.x) * 4;
    float4 v = *(const float4*)(src + i);
    __half2 a = __floats2half2_rn(v.x, v.y);
    __half2 b = __floats2half2_rn(v.z, v.w);
    *(uint2*)(dst + i) = make_uint2(*(unsigned*)&a, *(unsigned*)&b);
}

// All four W [K=DM][N=DM] -> W^T [N][K] fp16, one launch (grid.z = 4)
__global__ void tsplit4h(const float* __restrict__ W0, const float* __restrict__ W1,
                         const float* __restrict__ W2, const float* __restrict__ W3,
                         __half* __restrict__ T) {
    __shared__ float tile[32][33];
    const int z = blockIdx.z;
    const float* W = z == 0 ? W0 : (z == 1 ? W1 : (z == 2 ? W2 : W3));
    __half* t_out = T + (size_t)z * DM * DM;
    int k0 = blockIdx.y * 32, n0 = blockIdx.x * 32;
    int tx = threadIdx.x, ty = threadIdx.y;
#pragma unroll
    for (int j = 0; j < 32; j += 8)
        tile[ty + j][tx] = W[(size_t)(k0 + ty + j) * DM + n0 + tx];
    __syncthreads();
#pragma unroll
    for (int j = 0; j < 32; j += 8)
        t_out[(size_t)(n0 + ty + j) * DM + k0 + tx] = __float2half(tile[tx][ty + j]);
}

// ---------------------------------------------------------------------------
// Pipelined 1-pass fp16 HMMA GEMM. 256 thr (8 warps 2x4), tile 128x128, BK=16,
// 4-slot / 3-deep cp.async ring, SINGLE __syncthreads per iteration (refill
// targets slot (t+3)%4, whose readers finished at iter t-1, guarded by this
// iter's sync). FUSED epilogue writes q/k/v attention scratch; else fp32 out.
// m_base selects the row-half (multi-stream split).
// ---------------------------------------------------------------------------
#define ROWB    48
#define PLANEB  (128 * ROWB)        // 6144
#define STAGEB  (2 * PLANEB)        // 12288
#define NSTAGE  4
#define GSMEM   (NSTAGE * STAGEB)   // 49152

template <bool FUSED>
__global__ void __launch_bounds__(256, 2) gemm_fp16(
    const __half* __restrict__ A, const __half* __restrict__ BT,
    float* __restrict__ out, int m_base)
{
    extern __shared__ char dynsmem[];
    const uint32_t sb = smem_u32(dynsmem);
    const int tid = threadIdx.x, lane = tid & 31, warp = tid >> 5;
    const int m0 = m_base + blockIdx.y * 128;
    const int nb = blockIdx.x;
    const int nbase = nb * 128;
    const int col0 = (nb & 7) * 128;

    const int r = tid >> 1, hf = tid & 1;
    const __half* gsrcA = A  + (size_t)(m0 + r) * DM + hf * 8;
    const __half* gsrcB = BT + (size_t)(nbase + r) * DM + hf * 8;
    const uint32_t sdst = r * ROWB + hf * 16;

    const int wm = (warp >> 2) * 64, wn = (warp & 3) * 32;
    const int lrow = lane & 15, lcol = lane & 16;
    const uint32_t abase = (wm + lrow) * ROWB + lcol;
    const uint32_t bbase = (wn + lrow) * ROWB + lcol;

    float acc[4][4][4];
#pragma unroll
    for (int a = 0; a < 4; a++)
#pragma unroll
        for (int b = 0; b < 4; b++)
#pragma unroll
            for (int c = 0; c < 4; c++) acc[a][b][c] = 0.0f;

    // Prologue: tiles 0..2 into slots 0..2 (3-deep)
#pragma unroll
    for (int t = 0; t < 3; t++) {
        const uint32_t st = sb + t * STAGEB;
        const int kc = t * 16;
        CP16(st + sdst,          gsrcA + kc);
        CP16(st + PLANEB + sdst, gsrcB + kc);
        CP_COMMIT();
    }

    const int KT = DM / 16;  // 64
    for (int t = 0; t < KT; t++) {
        CP_WAIT2();
        __syncthreads();
        const uint32_t st = sb + (t % NSTAGE) * STAGEB;

        // Refill tile t+3 into slot (t+3)%4 (readers done at iter t-1)
        if (t + 3 < KT) {
            const uint32_t st2 = sb + ((t + 3) % NSTAGE) * STAGEB;
            const int kc = (t + 3) * 16;
            CP16(st2 + sdst,          gsrcA + kc);
            CP16(st2 + PLANEB + sdst, gsrcB + kc);
        }
        CP_COMMIT();

        unsigned bf[4][2];
#pragma unroll
        for (int j = 0; j < 2; j++) {
            unsigned r0, r1, r2, r3;
            LDSM4(r0, r1, r2, r3, st + PLANEB + bbase + j * (16 * ROWB));
            bf[2 * j][0] = r0; bf[2 * j + 1][0] = r1;
            bf[2 * j][1] = r2; bf[2 * j + 1][1] = r3;
        }
#pragma unroll
        for (int mt = 0; mt < 4; mt++) {
            unsigned af[4];
            LDSM4(af[0], af[1], af[2], af[3], st + abase + mt * (16 * ROWB));
#pragma unroll
            for (int nt = 0; nt < 4; nt++)
                mma_fp(acc[mt][nt], af, bf[nt]);
        }
    }

    const int g = lane >> 2, tig = lane & 3;
    if (!FUSED) {
#pragma unroll
        for (int mt = 0; mt < 4; mt++)
#pragma unroll
            for (int nt = 0; nt < 4; nt++) {
                int row = m0 + wm + mt * 16 + g;
                int cc = col0 + wn + nt * 8 + 2 * tig;
                *(float2*)(out + (size_t)row * DM + cc) =
                    make_float2(acc[mt][nt][0], acc[mt][nt][1]);
                *(float2*)(out + (size_t)(row + 8) * DM + cc) =
                    make_float2(acc[mt][nt][2], acc[mt][nt][3]);
            }
    } else {
        const int grp = nb >> 3;   // 0=q, 1=k, 2=v (uniform per block)
#pragma unroll
        for (int mt = 0; mt < 4; mt++)
#pragma unroll
            for (int nt = 0; nt < 4; nt++) {
                int row = m0 + wm + mt * 16 + g;
                int cc = col0 + wn + nt * 8 + 2 * tig;
                if (grp == 0) {
                    __half2 h0 = __floats2half2_rn(acc[mt][nt][0] * QSCALE,
                                                   acc[mt][nt][1] * QSCALE);
                    __half2 h1 = __floats2half2_rn(acc[mt][nt][2] * QSCALE,
                                                   acc[mt][nt][3] * QSCALE);
                    *(unsigned*)(g_qh + (size_t)row * DM + cc) = *(unsigned*)&h0;
                    *(unsigned*)(g_qh + (size_t)(row + 8) * DM + cc) = *(unsigned*)&h1;
                } else if (grp == 1) {
                    __half2 h0 = __floats2half2_rn(acc[mt][nt][0], acc[mt][nt][1]);
                    __half2 h1 = __floats2half2_rn(acc[mt][nt][2], acc[mt][nt][3]);
                    *(unsigned*)(g_kh + (size_t)row * DM + cc) = *(unsigned*)&h0;
                    *(unsigned*)(g_kh + (size_t)(row + 8) * DM + cc) = *(unsigned*)&h1;
                } else {
                    float a0 = acc[mt][nt][0], a1 = acc[mt][nt][1];
                    float a2 = acc[mt][nt][2], a3 = acc[mt][nt][3];
                    float b0 = __shfl_down_sync(0xffffffffu, a0, 4);
                    float b1 = __shfl_down_sync(0xffffffffu, a1, 4);
                    float b2 = __shfl_down_sync(0xffffffffu, a2, 4);
                    float b3 = __shfl_down_sync(0xffffffffu, a3, 4);
                    if (!(g & 1)) {
                        int prow = row >> 1;
                        __half2 p0 = __floats2half2_rn(a0, b0);
                        __half2 p1 = __floats2half2_rn(a1, b1);
                        *(uint2*)(g_vp + (size_t)prow * DM + cc) =
                            make_uint2(*(unsigned*)&p0, *(unsigned*)&p1);
                        __half2 p2 = __floats2half2_rn(a2, b2);
                        __half2 p3 = __floats2half2_rn(a3, b3);
                        *(uint2*)(g_vp + (size_t)(prow + 4) * DM + cc) =
                            make_uint2(*(unsigned*)&p2, *(unsigned*)&p3);
                    }
                }
            }
    }
}

// ---------------------------------------------------------------------------
// Warp-tiled flash attention. Chunk = 64 keys, fp16 QK^T and P@V, exp2 softmax.
// Masking only on boundary chunks (jc==t0 causal, jc==t0-WIN lower edge);
// interior chunks are provably fully valid. In the last chunk, key-blocks
// entirely below the warp's window are skipped (warp-uniform).
// qblk_off selects the query-block half (multi-stream split).
// ---------------------------------------------------------------------------
__global__ void __launch_bounds__(128, 4) attn_kernel(int qblk_off)
{
    __shared__ unsigned Qh[64][36];
    __shared__ unsigned Kh[64][36];
    __shared__ unsigned Vs[32][72];
    __shared__ unsigned Ps[64][36];

    const int h = blockIdx.y, t0 = (blockIdx.x + qblk_off) * 64;
    const int tid = threadIdx.x;
    const int lane = tid & 31, warp = tid >> 5;
    const int g = lane >> 2, tig = lane & 3;
    const int wq = t0 + warp * 16;
    const int rA = warp * 16 + g;

#pragma unroll
    for (int u = 0; u < 4; u++) {
        int idx = tid + u * 128;
        int r = idx >> 3, c = idx & 7;
        *(uint4*)&Qh[r][c * 4] =
            *(const uint4*)(g_qh + (size_t)(t0 + r) * DM + h * DH + c * 8);
    }

    float o[8][4];
#pragma unroll
    for (int nt = 0; nt < 8; nt++)
#pragma unroll
        for (int e = 0; e < 4; e++) o[nt][e] = 0.0f;
    float m0 = -1e30f, m1 = -1e30f, l0 = 0.0f, l1 = 0.0f;

    const int jlo = max(0, t0 - WIN);

    for (int jc = t0; jc >= jlo; jc -= 64) {
        __syncthreads();
#pragma unroll
        for (int u = 0; u < 4; u++) {
            int idx = tid + u * 128;
            int r = idx >> 3, c = idx & 7;
            *(uint4*)&Kh[r][c * 4] =
                *(const uint4*)(g_kh + (size_t)(jc + r) * DM + h * DH + c * 8);
        }
#pragma unroll
        for (int u = 0; u < 4; u++) {
            int idx = tid + u * 128;
            int r = idx >> 4, c = idx & 15;
            *(uint4*)&Vs[r][c * 4] =
                *(const uint4*)(g_vp + (size_t)((jc >> 1) + r) * DM + h * DH + c * 4);
        }
        __syncthreads();

        const bool is_first = (jc == t0);
        const bool is_last  = (jc == t0 - WIN);
        const int nt0 = is_last ? 2 * warp : 0;   // QK key-blocks fully below window
        const int ks0 = is_last ? warp : 0;       // PV key-pair-blocks fully below

        // Scores: S(16x64) = Q @ K^T
        float s[8][4];
#pragma unroll
        for (int nt = 0; nt < 8; nt++)
#pragma unroll
            for (int e = 0; e < 4; e++) s[nt][e] = 0.0f;
#pragma unroll
        for (int ks = 0; ks < 4; ks++) {
            unsigned qf[4];
            qf[0] = Qh[rA][ks * 8 + tig];     qf[1] = Qh[rA + 8][ks * 8 + tig];
            qf[2] = Qh[rA][ks * 8 + tig + 4]; qf[3] = Qh[rA + 8][ks * 8 + tig + 4];
#pragma unroll
            for (int nt = 0; nt < 8; nt++) {
                if (nt >= nt0) {
                    unsigned bf[2];
                    bf[0] = Kh[nt * 8 + g][ks * 8 + tig];
                    bf[1] = Kh[nt * 8 + g][ks * 8 + tig + 4];
                    mma_fp(s[nt], qf, bf);
                }
            }
        }

        const int r0 = wq + g, r1 = r0 + 8;
        if (is_first || is_last) {
#pragma unroll
            for (int nt = 0; nt < 8; nt++) {
#pragma unroll
                for (int e = 0; e < 2; e++) {
                    int j = jc + nt * 8 + 2 * tig + e;
                    if (j > r0 || j + WIN < r0) s[nt][e] = -1e30f;
                    if (j > r1 || j + WIN < r1) s[nt][2 + e] = -1e30f;
                }
            }
        }

        float mx0 = -1e30f, mx1 = -1e30f;
#pragma unroll
        for (int nt = 0; nt < 8; nt++) {
            mx0 = fmaxf(mx0, fmaxf(s[nt][0], s[nt][1]));
            mx1 = fmaxf(mx1, fmaxf(s[nt][2], s[nt][3]));
        }
        mx0 = fmaxf(mx0, __shfl_xor_sync(0xffffffffu, mx0, 1));
        mx0 = fmaxf(mx0, __shfl_xor_sync(0xffffffffu, mx0, 2));
        mx1 = fmaxf(mx1, __shfl_xor_sync(0xffffffffu, mx1, 1));
        mx1 = fmaxf(mx1, __shfl_xor_sync(0xffffffffu, mx1, 2));
        float mn0 = fmaxf(m0, mx0), mn1 = fmaxf(m1, mx1);
        float c0 = ex2(m0 - mn0), c1 = ex2(m1 - mn1);
        m0 = mn0; m1 = mn1;
        l0 *= c0; l1 *= c1;
#pragma unroll
        for (int nt = 0; nt < 8; nt++) {
            o[nt][0] *= c0; o[nt][1] *= c0;
            o[nt][2] *= c1; o[nt][3] *= c1;
        }
        float ls0 = 0.0f, ls1 = 0.0f;
#pragma unroll
        for (int nt = 0; nt < 8; nt++) {
            float p00 = ex2(s[nt][0] - mn0), p01 = ex2(s[nt][1] - mn0);
            float p10 = ex2(s[nt][2] - mn1), p11 = ex2(s[nt][3] - mn1);
            ls0 += p00 + p01; ls1 += p10 + p11;
            __half2 w0 = __floats2half2_rn(p00, p01);
            __half2 w1 = __floats2half2_rn(p10, p11);
            Ps[rA][nt * 4 + tig] = *(unsigned*)&w0;
            Ps[rA + 8][nt * 4 + tig] = *(unsigned*)&w1;
        }
        ls0 += __shfl_xor_sync(0xffffffffu, ls0, 1);
        ls0 += __shfl_xor_sync(0xffffffffu, ls0, 2);
        ls1 += __shfl_xor_sync(0xffffffffu, ls1, 1);
        ls1 += __shfl_xor_sync(0xffffffffu, ls1, 2);
        l0 += ls0; l1 += ls1;
        __syncwarp();

        // O += P(16x64) @ V(64x64)
#pragma unroll
        for (int ks2 = 0; ks2 < 4; ks2++) {
            if (ks2 >= ks0) {
                unsigned pa[4];
                pa[0] = Ps[rA][ks2 * 8 + tig];
                pa[1] = Ps[rA + 8][ks2 * 8 + tig];
                pa[2] = Ps[rA][ks2 * 8 + tig + 4];
                pa[3] = Ps[rA + 8][ks2 * 8 + tig + 4];
#pragma unroll
                for (int nt = 0; nt < 8; nt++) {
                    unsigned vb[2];
                    vb[0] = Vs[ks2 * 8 + tig][nt * 8 + g];
                    vb[1] = Vs[ks2 * 8 + tig + 4][nt * 8 + g];
                    mma_fp(o[nt], pa, vb);
                }
            }
        }
    }

    const float inv0 = 1.0f / l0, inv1 = 1.0f / l1;
#pragma unroll
    for (int nt = 0; nt < 8; nt++) {
        int col = h * DH + nt * 8 + 2 * tig;
        __half2 a = __floats2half2_rn(o[nt][0] * inv0, o[nt][1] * inv0);
        __half2 b = __floats2half2_rn(o[nt][2] * inv1, o[nt][3] * inv1);
        *(unsigned*)(g_ao + (size_t)(wq + g) * DM + col) = *(unsigned*)&a;
        *(unsigned*)(g_ao + (size_t)(wq + g + 8) * DM + col) = *(unsigned*)&b;
    }
}

// ---------------------------------------------------------------------------
// Launch: row-halved pipeline on two streams.
//   legacy: conv -> QKV-A -> attnA -> O-A -> (join) -> O-B
//   s2 (low prio): QKV-B -> attnB
// attnA needs only rows 0..2047 (t0+63 <= 2047, window >= 0). attnB needs
// both halves. O-A needs only attnA. All forked work joins legacy via event.
// ---------------------------------------------------------------------------
extern "C" void kernel_launch(void* const* d_in, const int* in_sizes, int n_in,
                              void* d_out, int out_size)
{
    const float* x  = (const float*)d_in[0];
    const float* Wq = (const float*)d_in[1];
    const float* Wk = (const float*)d_in[2];
    const float* Wv = (const float*)d_in[3];
    const float* Wo = (const float*)d_in[4];
    float* out = (float*)d_out;

    __half *xh, *ao, *wt;
    cudaGetSymbolAddress((void**)&xh, g_xh);
    cudaGetSymbolAddress((void**)&ao, g_ao);
    cudaGetSymbolAddress((void**)&wt, g_wt);

    cudaFuncSetAttribute(gemm_fp16<true>,  cudaFuncAttributeMaxDynamicSharedMemorySize, GSMEM);
    cudaFuncSetAttribute(gemm_fp16<false>, cudaFuncAttributeMaxDynamicSharedMemorySize, GSMEM);

    int prLo = 0, prHi = 0;
    cudaDeviceGetStreamPriorityRange(&prLo, &prHi);   // prLo = least urgent
    cudaStream_t s2;
    cudaStreamCreateWithPriority(&s2, cudaStreamNonBlocking, prLo);
    cudaEvent_t evConv, evA, evB;
    cudaEventCreateWithFlags(&evConv, cudaEventDisableTiming);
    cudaEventCreateWithFlags(&evA,    cudaEventDisableTiming);
    cudaEventCreateWithFlags(&evB,    cudaEventDisableTiming);

    // One-time conversions (legacy stream)
    tsplit4h<<<dim3(DM / 32, DM / 32, 4), dim3(32, 8)>>>(Wq, Wk, Wv, Wo, wt);
    tohalf<<<SEQ * DM / 1024, 256>>>(x, xh);
    cudaEventRecord(evConv, 0);
    cudaStreamWaitEvent(s2, evConv, 0);

    // QKV GEMM, row-halved: A on legacy (high prio), B on s2 (low prio)
    gemm_fp16<true><<<dim3(24, SEQ / 256), 256, GSMEM, 0>>>(xh, wt, nullptr, 0);
    gemm_fp16<true><<<dim3(24, SEQ / 256), 256, GSMEM, s2>>>(xh, wt, nullptr, SEQ / 2);
    cudaEventRecord(evA, 0);

    // Attention halves
    attn_kernel<<<dim3(32, NH), 128, 0, 0>>>(0);          // rows 0..2047 only
    cudaStreamWaitEvent(s2, evA, 0);
    attn_kernel<<<dim3(32, NH), 128, 0, s2>>>(32);        // needs both halves

    // O-projection halves
    gemm_fp16<false><<<dim3(8, SEQ / 256), 256, GSMEM, 0>>>(
        ao, wt + 3 * (size_t)DM * DM, out, 0);
    cudaEventRecord(evB, s2);
    cudaStreamWaitEvent(0, evB, 0);                        // join fork
    gemm_fp16<false><<<dim3(8, SEQ / 256), 256, GSMEM, 0>>>(
        ao, wt + 3 * (size_t)DM * DM, out, SEQ / 2);
}